// round 3
// baseline (speedup 1.0000x reference)
#include <cuda_runtime.h>
#include <cuda_bf16.h>
#include <math.h>

#define BB   256
#define TT   512
#define IN_D 32
#define HH   128
#define SS   4
#define DTC  0.1f

// device-global scratch (allocation-free)
__device__ float g_xproj[(size_t)BB * TT * HH];   // 64 MB, [b][t][h]
__device__ float g_hT[SS * BB * HH];

// ---------------- shared layout for liquid kernel (float offsets) ----------
#define OFF_WR   0
#define OFF_WI   16896          // 128*132
#define OFF_V1   33792          // +128*132
#define OFF_V2   38016          // +32*132
#define OFF_H    42624          // +128*36
#define OFF_X    44160          // +12*128
#define OFF_QP   45696          // +12*128
#define OFF_QS   47232          // +12*32*4
#define OFF_RED  47616          // +12*32
#define OFF_BC   47664          // +12*4
#define OFF_TB   47792
#define OFF_V2B  47920
#define OFF_V1B  48048
#define SMEM_FLOATS 48080
#define SMEM_BYTES (SMEM_FLOATS * 4)

// ---------------------------------------------------------------------------
// K1: x_proj = x @ Wp^T + bp   (rows = B*T)
// ---------------------------------------------------------------------------
__global__ __launch_bounds__(128) void xproj_kernel(
    const float* __restrict__ x, const float* __restrict__ Wp,
    const float* __restrict__ bp)
{
    __shared__ float sW[128 * 36];
    __shared__ float sx[32 * 32];
    __shared__ float sb[128];
    const int tid = threadIdx.x;

    for (int idx = tid; idx < 128 * 32; idx += 128) {
        int j = idx >> 5, k = idx & 31;
        sW[j * 36 + k] = Wp[idx];
    }
    sb[tid] = bp[tid];
    const size_t base = (size_t)blockIdx.x * 32;
    for (int idx = tid; idx < 1024; idx += 128)
        sx[idx] = x[base * 32 + idx];
    __syncthreads();

    float acc[32];
    const float b = sb[tid];
    #pragma unroll
    for (int r = 0; r < 32; r++) acc[r] = b;

    #pragma unroll 2
    for (int kk = 0; kk < 32; kk += 4) {
        const float4 w4 = *(const float4*)&sW[tid * 36 + kk];
        #pragma unroll
        for (int r = 0; r < 32; r++) {
            const float4 x4 = *(const float4*)&sx[r * 32 + kk];
            acc[r] = fmaf(x4.x, w4.x, acc[r]);
            acc[r] = fmaf(x4.y, w4.y, acc[r]);
            acc[r] = fmaf(x4.z, w4.z, acc[r]);
            acc[r] = fmaf(x4.w, w4.w, acc[r]);
        }
    }
    #pragma unroll
    for (int r = 0; r < 32; r++)
        g_xproj[(base + r) * HH + tid] = acc[r];
}

// ---------------------------------------------------------------------------
// K2: persistent liquid-cell recurrence. One block = (scale, R-row chunk).
// 128 threads; thread j owns hidden column j.
// ---------------------------------------------------------------------------
template<int R, int NS>
__device__ __forceinline__ void run_cell(
    const float* __restrict__ Wrec, const float* __restrict__ Win_w,
    const float* __restrict__ Win_b, const float* __restrict__ cbias,
    const float* __restrict__ tau_base,
    const float* __restrict__ v1w, const float* __restrict__ v1b,
    const float* __restrict__ v2w, const float* __restrict__ v2b,
    int s, int row0)
{
    extern __shared__ float sm[];
    float* sWr  = sm + OFF_WR;
    float* sWi  = sm + OFF_WI;
    float* sV1  = sm + OFF_V1;
    float* sV2  = sm + OFF_V2;
    float* sh   = sm + OFF_H;
    float* sx   = sm + OFF_X;
    float* sqp  = sm + OFF_QP;
    float* sqs  = sm + OFF_QS;
    float* sred = sm + OFF_RED;
    float* sbc  = sm + OFF_BC;
    float* stb  = sm + OFF_TB;
    float* sv2b = sm + OFF_V2B;
    float* sv1b = sm + OFF_V1B;

    const int tid = threadIdx.x;
    const int w = tid >> 5, l = tid & 31;

    // stage all time-invariant weights into SMEM
    const float* Wr = Wrec + s * 16384;
    const float* Wi = Win_w + s * 16384;
    for (int idx = tid; idx < 16384; idx += 128) {
        int j = idx >> 7, k = idx & 127;
        sWr[j * 132 + k] = Wr[idx];
        sWi[j * 132 + k] = Wi[idx];
    }
    for (int idx = tid; idx < 32 * 128; idx += 128) {
        int j = idx >> 7, k = idx & 127;
        sV1[j * 132 + k] = v1w[s * 4096 + idx];
    }
    for (int idx = tid; idx < 128 * 32; idx += 128) {
        int j = idx >> 5, k = idx & 31;
        sV2[j * 36 + k] = v2w[s * 4096 + idx];
    }
    sbc[tid]  = Win_b[s * 128 + tid] + cbias[s * 128 + tid];
    stb[tid]  = tau_base[s * 128 + tid];
    sv2b[tid] = v2b[s * 128 + tid];
    if (tid < 32) sv1b[tid] = v1b[s * 32 + tid];

    float hj[R];
    int rows[R];
    #pragma unroll
    for (int r = 0; r < R; r++) {
        hj[r] = 0.f;
        sh[r * 128 + tid] = 0.f;
        rows[r] = min(row0 + r, BB - 1);    // clamp ragged tail
    }
    const float tb = tau_base[s * 128 + tid];
    __syncthreads();

    for (int t = 0; t < TT; t++) {
        // stage x_t for R rows (L2-hit: g_xproj fits in L2)
        #pragma unroll
        for (int r = 0; r < R; r++)
            sx[r * 128 + tid] = g_xproj[((size_t)rows[r] * TT + t) * HH + tid];
        __syncthreads();

        // ---- volatility gate layer 1 partials: k-split across 4 warps ----
        {
            float qp[R];
            #pragma unroll
            for (int r = 0; r < R; r++) qp[r] = 0.f;
            const int k0 = w * 32;
            #pragma unroll 2
            for (int kk = 0; kk < 32; kk += 4) {
                const float4 v4 = *(const float4*)&sV1[l * 132 + k0 + kk];
                #pragma unroll
                for (int r = 0; r < R; r++) {
                    const float4 x4 = *(const float4*)&sx[r * 128 + k0 + kk];
                    qp[r] = fmaf(x4.x, v4.x, qp[r]);
                    qp[r] = fmaf(x4.y, v4.y, qp[r]);
                    qp[r] = fmaf(x4.z, v4.z, qp[r]);
                    qp[r] = fmaf(x4.w, v4.w, qp[r]);
                }
            }
            #pragma unroll
            for (int r = 0; r < R; r++) sqp[(r * 32 + l) * 4 + w] = qp[r];
        }
        __syncthreads();
        if (tid < 32) {
            #pragma unroll
            for (int r = 0; r < R; r++) {
                const float4 p4 = *(const float4*)&sqp[(r * 32 + tid) * 4];
                float q = p4.x + p4.y + p4.z + p4.w + sv1b[tid];
                sqs[r * 32 + tid] = fmaxf(q, 0.f);
            }
        }
        __syncthreads();

        // ---- gate layer 2 -> tau; inp GEMM ----
        float rtau[R], inp[R];
        {
            float va[R];
            #pragma unroll
            for (int r = 0; r < R; r++) va[r] = sv2b[tid];
            #pragma unroll 2
            for (int ii = 0; ii < 32; ii += 4) {
                const float4 w4 = *(const float4*)&sV2[tid * 36 + ii];
                #pragma unroll
                for (int r = 0; r < R; r++) {
                    const float4 q4 = *(const float4*)&sqs[r * 32 + ii];
                    va[r] = fmaf(q4.x, w4.x, va[r]);
                    va[r] = fmaf(q4.y, w4.y, va[r]);
                    va[r] = fmaf(q4.z, w4.z, va[r]);
                    va[r] = fmaf(q4.w, w4.w, va[r]);
                }
            }
            #pragma unroll
            for (int r = 0; r < R; r++) {
                const float vol = 1.f / (1.f + __expf(-va[r]));
                float ta = tb * (0.2f + 1.8f * (1.f - vol));
                ta = fminf(fmaxf(ta, 0.1f), 10.f);
                rtau[r] = __frcp_rn(ta);
            }
            #pragma unroll
            for (int r = 0; r < R; r++) inp[r] = sbc[tid];
            #pragma unroll 4
            for (int kk = 0; kk < 128; kk += 4) {
                const float4 w4 = *(const float4*)&sWi[tid * 132 + kk];
                #pragma unroll
                for (int r = 0; r < R; r++) {
                    const float4 x4 = *(const float4*)&sx[r * 128 + kk];
                    inp[r] = fmaf(x4.x, w4.x, inp[r]);
                    inp[r] = fmaf(x4.y, w4.y, inp[r]);
                    inp[r] = fmaf(x4.z, w4.z, inp[r]);
                    inp[r] = fmaf(x4.w, w4.w, inp[r]);
                }
            }
        }

        // ---- inner ODE steps ----
        #pragma unroll 1
        for (int it = 0; it < NS; it++) {
            float acc[R];
            #pragma unroll
            for (int r = 0; r < R; r++) acc[r] = inp[r];
            #pragma unroll 4
            for (int kk = 0; kk < 128; kk += 4) {
                const float4 w4 = *(const float4*)&sWr[tid * 132 + kk];
                #pragma unroll
                for (int r = 0; r < R; r++) {
                    const float4 h4 = *(const float4*)&sh[r * 128 + kk];
                    acc[r] = fmaf(h4.x, w4.x, acc[r]);
                    acc[r] = fmaf(h4.y, w4.y, acc[r]);
                    acc[r] = fmaf(h4.z, w4.z, acc[r]);
                    acc[r] = fmaf(h4.w, w4.w, acc[r]);
                }
            }
            float d[R];
            #pragma unroll
            for (int r = 0; r < R; r++) {
                const float target = tanhf(acc[r]);
                d[r] = (target - hj[r]) * rtau[r];
            }
            #pragma unroll
            for (int r = 0; r < R; r++) {
                float sq = d[r] * d[r];
                sq += __shfl_xor_sync(0xffffffffu, sq, 16);
                sq += __shfl_xor_sync(0xffffffffu, sq, 8);
                sq += __shfl_xor_sync(0xffffffffu, sq, 4);
                sq += __shfl_xor_sync(0xffffffffu, sq, 2);
                sq += __shfl_xor_sync(0xffffffffu, sq, 1);
                if (l == 0) sred[r * 4 + w] = sq;
            }
            __syncthreads();
            #pragma unroll
            for (int r = 0; r < R; r++) {
                const float4 s4 = *(const float4*)&sred[r * 4];
                const float mag = sqrtf(s4.x + s4.y + s4.z + s4.w);
                const float coef = DTC / (1.f + 0.2f * mag);
                hj[r] = fmaf(coef, d[r], hj[r]);
                sh[r * 128 + tid] = hj[r];
            }
            __syncthreads();
        }
    }

    #pragma unroll
    for (int r = 0; r < R; r++)
        if (row0 + r < BB)
            g_hT[(s * BB + row0 + r) * HH + tid] = hj[r];
}

__global__ __launch_bounds__(128, 1) void liquid_kernel(
    const float* __restrict__ Wrec, const float* __restrict__ Win_w,
    const float* __restrict__ Win_b, const float* __restrict__ cbias,
    const float* __restrict__ tau_base,
    const float* __restrict__ v1w, const float* __restrict__ v1b,
    const float* __restrict__ v2w, const float* __restrict__ v2b)
{
    const int b = blockIdx.x;
    if (b < 22)
        run_cell<12, 3>(Wrec, Win_w, Win_b, cbias, tau_base, v1w, v1b, v2w, v2b, 0, b * 12);
    else if (b < 54)
        run_cell<8, 5>(Wrec, Win_w, Win_b, cbias, tau_base, v1w, v1b, v2w, v2b, 1, (b - 22) * 8);
    else if (b < 91)
        run_cell<7, 7>(Wrec, Win_w, Win_b, cbias, tau_base, v1w, v1b, v2w, v2b, 2, (b - 54) * 7);
    else
        run_cell<5, 9>(Wrec, Win_w, Win_b, cbias, tau_base, v1w, v1b, v2w, v2b, 3, (b - 91) * 5);
}

// ---------------------------------------------------------------------------
// K3: per-scale projection + concat + fusion MLP. One block per batch row.
// ---------------------------------------------------------------------------
__global__ __launch_bounds__(128) void head_kernel(
    const float* __restrict__ proj_w, const float* __restrict__ proj_b,
    const float* __restrict__ f1w, const float* __restrict__ f1b,
    const float* __restrict__ f2w, const float* __restrict__ f2b,
    const float* __restrict__ f3w, const float* __restrict__ f3b,
    float* __restrict__ out)
{
    __shared__ float fused[128];
    __shared__ float h1[128];
    __shared__ float h2[64];
    __shared__ float part[2];
    const int b = blockIdx.x;
    const int j = threadIdx.x;
    const int s = j >> 5, i = j & 31;

    // feats[s][i] = hT[s][b] . proj_w[s][i]
    {
        const float* h = &g_hT[(s * BB + b) * HH];
        const float* pw = &proj_w[(s * 32 + i) * HH];
        float a = proj_b[s * 32 + i];
        #pragma unroll 8
        for (int k = 0; k < 128; k++) a = fmaf(h[k], pw[k], a);
        fused[j] = a;
    }
    __syncthreads();
    {
        float a = f1b[j];
        const float* wrow = &f1w[j * 128];
        #pragma unroll 8
        for (int k = 0; k < 128; k++) a = fmaf(fused[k], wrow[k], a);
        h1[j] = fmaxf(a, 0.f);
    }
    __syncthreads();
    if (j < 64) {
        float a = f2b[j];
        const float* wrow = &f2w[j * 128];
        #pragma unroll 8
        for (int k = 0; k < 128; k++) a = fmaf(h1[k], wrow[k], a);
        h2[j] = fmaxf(a, 0.f);
    }
    __syncthreads();
    if (j < 64) {
        float p = h2[j] * f3w[j];
        p += __shfl_xor_sync(0xffffffffu, p, 16);
        p += __shfl_xor_sync(0xffffffffu, p, 8);
        p += __shfl_xor_sync(0xffffffffu, p, 4);
        p += __shfl_xor_sync(0xffffffffu, p, 2);
        p += __shfl_xor_sync(0xffffffffu, p, 1);
        if ((j & 31) == 0) part[j >> 5] = p;
    }
    __syncthreads();
    if (j == 0) out[b] = part[0] + part[1] + f3b[0];
}

// ---------------------------------------------------------------------------
extern "C" void kernel_launch(void* const* d_in, const int* in_sizes, int n_in,
                              void* d_out, int out_size)
{
    const float* x        = (const float*)d_in[0];
    const float* Wp       = (const float*)d_in[1];
    const float* bp       = (const float*)d_in[2];
    const float* Wrec     = (const float*)d_in[3];
    const float* Win_w    = (const float*)d_in[4];
    const float* Win_b    = (const float*)d_in[5];
    const float* cbias    = (const float*)d_in[6];
    const float* tau_base = (const float*)d_in[7];
    const float* vg1_w    = (const float*)d_in[8];
    const float* vg1_b    = (const float*)d_in[9];
    const float* vg2_w    = (const float*)d_in[10];
    const float* vg2_b    = (const float*)d_in[11];
    const float* proj_w   = (const float*)d_in[12];
    const float* proj_b   = (const float*)d_in[13];
    const float* f1w      = (const float*)d_in[14];
    const float* f1b      = (const float*)d_in[15];
    const float* f2w      = (const float*)d_in[16];
    const float* f2b      = (const float*)d_in[17];
    const float* f3w      = (const float*)d_in[18];
    const float* f3b      = (const float*)d_in[19];
    float* out = (float*)d_out;

    cudaFuncSetAttribute(liquid_kernel,
                         cudaFuncAttributeMaxDynamicSharedMemorySize, SMEM_BYTES);

    xproj_kernel<<<(BB * TT) / 32, 128>>>(x, Wp, bp);
    liquid_kernel<<<143, 128, SMEM_BYTES>>>(Wrec, Win_w, Win_b, cbias, tau_base,
                                            vg1_w, vg1_b, vg2_w, vg2_b);
    head_kernel<<<BB, 128>>>(proj_w, proj_b, f1w, f1b, f2w, f2b, f3w, f3b, out);
}

// round 4
// speedup vs baseline: 1.1334x; 1.1334x over previous
#include <cuda_runtime.h>
#include <cuda_bf16.h>
#include <math.h>

#define BB   256
#define TT   512
#define HH   128
#define SS   4
#define DTC  0.1f

// device-global scratch (allocation-free)
__device__ float g_xproj[(size_t)BB * TT * HH];   // 64 MB, [b][t][h] — fits L2
__device__ float g_hT[SS * BB * HH];

// ---- shared layout (float offsets) ----
#define OFF_WR   0            // 128*132
#define OFF_WI   16896        // 128*132
#define OFF_V1   33792        // 32*132
#define OFF_V2   38016        // 128*36
#define OFF_BC   42624        // 128
#define OFF_V2B  42752        // 128
#define OFF_V1B  42880        // 32
#define OFF_GRP  42912
#define GRP_STRIDE 2944       // per-group: sh 896 | sx 896 | qp 896 | qs 224 | red 28(+pad)
#define SMEM_FLOATS (OFF_GRP + 2 * GRP_STRIDE)
#define SMEM_BYTES  (SMEM_FLOATS * 4)

__device__ __forceinline__ float fast_tanh(float x) {
    float ax = fminf(fabsf(x), 12.0f);
    float e  = __expf(2.0f * ax);
    float r  = __fdividef(e - 1.0f, e + 1.0f);
    return copysignf(r, x);
}

// ---------------------------------------------------------------------------
// K1: x_proj = x @ Wp^T + bp
// ---------------------------------------------------------------------------
__global__ __launch_bounds__(128) void xproj_kernel(
    const float* __restrict__ x, const float* __restrict__ Wp,
    const float* __restrict__ bp)
{
    __shared__ float sW[128 * 36];
    __shared__ float sx[32 * 32];
    __shared__ float sb[128];
    const int tid = threadIdx.x;

    for (int idx = tid; idx < 128 * 32; idx += 128) {
        int j = idx >> 5, k = idx & 31;
        sW[j * 36 + k] = Wp[idx];
    }
    sb[tid] = bp[tid];
    const size_t base = (size_t)blockIdx.x * 32;
    for (int idx = tid; idx < 1024; idx += 128)
        sx[idx] = x[base * 32 + idx];
    __syncthreads();

    float acc[32];
    const float b = sb[tid];
    #pragma unroll
    for (int r = 0; r < 32; r++) acc[r] = b;

    #pragma unroll 2
    for (int kk = 0; kk < 32; kk += 4) {
        const float4 w4 = *(const float4*)&sW[tid * 36 + kk];
        #pragma unroll
        for (int r = 0; r < 32; r++) {
            const float4 x4 = *(const float4*)&sx[r * 32 + kk];
            acc[r] = fmaf(x4.x, w4.x, acc[r]);
            acc[r] = fmaf(x4.y, w4.y, acc[r]);
            acc[r] = fmaf(x4.z, w4.z, acc[r]);
            acc[r] = fmaf(x4.w, w4.w, acc[r]);
        }
    }
    #pragma unroll
    for (int r = 0; r < 32; r++)
        g_xproj[(base + r) * HH + tid] = acc[r];
}

// ---------------------------------------------------------------------------
// K2: persistent liquid recurrence. 256 threads = two independent 128-thread
// groups (own rows, named barriers) sharing one SMEM weight copy.
// Within a group: thread j owns hidden column j for G rows.
// ---------------------------------------------------------------------------
template<int G, int NS>
__device__ __forceinline__ void run_group(
    const float* __restrict__ tau_base, int s, int grow0)
{
    extern __shared__ float sm[];
    const int tid  = threadIdx.x;
    const int g    = tid >> 7;
    const int gtid = tid & 127;
    const int w = gtid >> 5, l = gtid & 31;

    float* gs   = sm + OFF_GRP + g * GRP_STRIDE;
    float* sh   = gs;
    float* sx   = gs + 896;
    float* sqp  = gs + 1792;
    float* sqs  = gs + 2688;
    float* sred = gs + 2912;
    const float* sWr  = sm + OFF_WR;
    const float* sWi  = sm + OFF_WI;
    const float* sV1  = sm + OFF_V1;
    const float* sV2  = sm + OFF_V2;
    const float* sbc  = sm + OFF_BC;
    const float* sv2b = sm + OFF_V2B;
    const float* sv1b = sm + OFF_V1B;

    const int barid = g + 1;
    #define GBAR() asm volatile("bar.sync %0, 128;" :: "r"(barid) : "memory")

    const float tb = tau_base[s * 128 + gtid];
    float hj[G];
    int rows[G];
    #pragma unroll
    for (int r = 0; r < G; r++) {
        hj[r] = 0.f;
        sh[r * 128 + gtid] = 0.f;
        rows[r] = min(grow0 + r, BB - 1);
    }
    GBAR();

    for (int t = 0; t < TT; t++) {
        #pragma unroll
        for (int r = 0; r < G; r++)
            sx[r * 128 + gtid] = g_xproj[((size_t)rows[r] * TT + t) * HH + gtid];
        GBAR();

        // gate layer 1, k-split across 4 warps of the group
        {
            float qp[G];
            #pragma unroll
            for (int r = 0; r < G; r++) qp[r] = 0.f;
            const int k0 = w * 32;
            #pragma unroll 2
            for (int kk = 0; kk < 32; kk += 4) {
                const float4 v4 = *(const float4*)&sV1[l * 132 + k0 + kk];
                #pragma unroll
                for (int r = 0; r < G; r++) {
                    const float4 x4 = *(const float4*)&sx[r * 128 + k0 + kk];
                    qp[r] = fmaf(x4.x, v4.x, qp[r]);
                    qp[r] = fmaf(x4.y, v4.y, qp[r]);
                    qp[r] = fmaf(x4.z, v4.z, qp[r]);
                    qp[r] = fmaf(x4.w, v4.w, qp[r]);
                }
            }
            #pragma unroll
            for (int r = 0; r < G; r++) sqp[(r * 32 + l) * 4 + w] = qp[r];
        }
        GBAR();
        if (gtid < 32) {
            #pragma unroll
            for (int r = 0; r < G; r++) {
                const float4 p4 = *(const float4*)&sqp[(r * 32 + gtid) * 4];
                sqs[r * 32 + gtid] = fmaxf(p4.x + p4.y + p4.z + p4.w + sv1b[gtid], 0.f);
            }
        }
        GBAR();

        // gate layer 2 -> tau; inp GEMM
        float rtau[G], inp[G];
        {
            float va[G];
            #pragma unroll
            for (int r = 0; r < G; r++) va[r] = sv2b[gtid];
            #pragma unroll 2
            for (int ii = 0; ii < 32; ii += 4) {
                const float4 w4 = *(const float4*)&sV2[gtid * 36 + ii];
                #pragma unroll
                for (int r = 0; r < G; r++) {
                    const float4 q4 = *(const float4*)&sqs[r * 32 + ii];
                    va[r] = fmaf(q4.x, w4.x, va[r]);
                    va[r] = fmaf(q4.y, w4.y, va[r]);
                    va[r] = fmaf(q4.z, w4.z, va[r]);
                    va[r] = fmaf(q4.w, w4.w, va[r]);
                }
            }
            #pragma unroll
            for (int r = 0; r < G; r++) {
                const float vol = __fdividef(1.f, 1.f + __expf(-va[r]));
                float ta = tb * (0.2f + 1.8f * (1.f - vol));
                ta = fminf(fmaxf(ta, 0.1f), 10.f);
                rtau[r] = __frcp_rn(ta);
            }
            #pragma unroll
            for (int r = 0; r < G; r++) inp[r] = sbc[gtid];
            #pragma unroll 4
            for (int kk = 0; kk < 128; kk += 4) {
                const float4 w4 = *(const float4*)&sWi[gtid * 132 + kk];
                #pragma unroll
                for (int r = 0; r < G; r++) {
                    const float4 x4 = *(const float4*)&sx[r * 128 + kk];
                    inp[r] = fmaf(x4.x, w4.x, inp[r]);
                    inp[r] = fmaf(x4.y, w4.y, inp[r]);
                    inp[r] = fmaf(x4.z, w4.z, inp[r]);
                    inp[r] = fmaf(x4.w, w4.w, inp[r]);
                }
            }
        }

        // inner ODE steps
        #pragma unroll 1
        for (int it = 0; it < NS; it++) {
            float acc[G];
            #pragma unroll
            for (int r = 0; r < G; r++) acc[r] = inp[r];
            #pragma unroll 4
            for (int kk = 0; kk < 128; kk += 4) {
                const float4 w4 = *(const float4*)&sWr[gtid * 132 + kk];
                #pragma unroll
                for (int r = 0; r < G; r++) {
                    const float4 h4 = *(const float4*)&sh[r * 128 + kk];
                    acc[r] = fmaf(h4.x, w4.x, acc[r]);
                    acc[r] = fmaf(h4.y, w4.y, acc[r]);
                    acc[r] = fmaf(h4.z, w4.z, acc[r]);
                    acc[r] = fmaf(h4.w, w4.w, acc[r]);
                }
            }
            float d[G];
            #pragma unroll
            for (int r = 0; r < G; r++)
                d[r] = (fast_tanh(acc[r]) - hj[r]) * rtau[r];
            #pragma unroll
            for (int r = 0; r < G; r++) {
                float sq = d[r] * d[r];
                sq += __shfl_xor_sync(0xffffffffu, sq, 16);
                sq += __shfl_xor_sync(0xffffffffu, sq, 8);
                sq += __shfl_xor_sync(0xffffffffu, sq, 4);
                sq += __shfl_xor_sync(0xffffffffu, sq, 2);
                sq += __shfl_xor_sync(0xffffffffu, sq, 1);
                if (l == 0) sred[r * 4 + w] = sq;
            }
            GBAR();
            #pragma unroll
            for (int r = 0; r < G; r++) {
                const float4 s4 = *(const float4*)&sred[r * 4];
                const float mag = sqrtf(s4.x + s4.y + s4.z + s4.w);
                const float coef = __fdividef(DTC, 1.f + 0.2f * mag);
                hj[r] = fmaf(coef, d[r], hj[r]);
                sh[r * 128 + gtid] = hj[r];
            }
            GBAR();
        }
    }

    #pragma unroll
    for (int r = 0; r < G; r++)
        g_hT[(s * BB + rows[r]) * HH + gtid] = hj[r];
    #undef GBAR
}

__global__ __launch_bounds__(256, 1) void liquid_kernel(
    const float* __restrict__ Wrec, const float* __restrict__ Win_w,
    const float* __restrict__ Win_b, const float* __restrict__ cbias,
    const float* __restrict__ tau_base,
    const float* __restrict__ v1w, const float* __restrict__ v1b,
    const float* __restrict__ v2w, const float* __restrict__ v2b)
{
    extern __shared__ float sm[];
    const int tid = threadIdx.x;
    const int b = blockIdx.x;

    int s, row0;
    if      (b < 21) { s = 0; row0 = b * 13; }
    else if (b < 53) { s = 1; row0 = (b - 21) * 8; }
    else if (b < 96) { s = 2; row0 = (b - 53) * 6; }
    else             { s = 3; row0 = (b - 96) * 5; }

    // stage time-invariant weights (shared by both groups)
    const float* Wr = Wrec  + s * 16384;
    const float* Wi = Win_w + s * 16384;
    for (int idx = tid; idx < 16384; idx += 256) {
        int j = idx >> 7, k = idx & 127;
        sm[OFF_WR + j * 132 + k] = Wr[idx];
        sm[OFF_WI + j * 132 + k] = Wi[idx];
    }
    for (int idx = tid; idx < 32 * 128; idx += 256) {
        int j = idx >> 7, k = idx & 127;
        sm[OFF_V1 + j * 132 + k] = v1w[s * 4096 + idx];
    }
    for (int idx = tid; idx < 128 * 32; idx += 256) {
        int j = idx >> 5, k = idx & 31;
        sm[OFF_V2 + j * 36 + k] = v2w[s * 4096 + idx];
    }
    if (tid < 128) {
        sm[OFF_BC  + tid] = Win_b[s * 128 + tid] + cbias[s * 128 + tid];
        sm[OFF_V2B + tid] = v2b[s * 128 + tid];
        if (tid < 32) sm[OFF_V1B + tid] = v1b[s * 32 + tid];
    }
    __syncthreads();

    const int g = tid >> 7;
    if      (b < 21) { if (!g) run_group<7, 3>(tau_base, 0, row0);
                       else    run_group<6, 3>(tau_base, 0, row0 + 7); }
    else if (b < 53) {          run_group<4, 5>(tau_base, 1, row0 + g * 4); }
    else if (b < 96) {          run_group<3, 7>(tau_base, 2, row0 + g * 3); }
    else             { if (!g) run_group<3, 9>(tau_base, 3, row0);
                       else    run_group<2, 9>(tau_base, 3, row0 + 3); }
}

// ---------------------------------------------------------------------------
// K3: projection + concat + fusion MLP. One block per batch row.
// ---------------------------------------------------------------------------
__global__ __launch_bounds__(128) void head_kernel(
    const float* __restrict__ proj_w, const float* __restrict__ proj_b,
    const float* __restrict__ f1w, const float* __restrict__ f1b,
    const float* __restrict__ f2w, const float* __restrict__ f2b,
    const float* __restrict__ f3w, const float* __restrict__ f3b,
    float* __restrict__ out)
{
    __shared__ float fused[128];
    __shared__ float h1[128];
    __shared__ float h2[64];
    __shared__ float part[2];
    const int b = blockIdx.x;
    const int j = threadIdx.x;
    const int s = j >> 5, i = j & 31;

    {
        const float* h  = &g_hT[(s * BB + b) * HH];
        const float* pw = &proj_w[(s * 32 + i) * HH];
        float a = proj_b[s * 32 + i];
        #pragma unroll 8
        for (int k = 0; k < 128; k++) a = fmaf(h[k], pw[k], a);
        fused[j] = a;
    }
    __syncthreads();
    {
        float a = f1b[j];
        const float* wrow = &f1w[j * 128];
        #pragma unroll 8
        for (int k = 0; k < 128; k++) a = fmaf(fused[k], wrow[k], a);
        h1[j] = fmaxf(a, 0.f);
    }
    __syncthreads();
    if (j < 64) {
        float a = f2b[j];
        const float* wrow = &f2w[j * 128];
        #pragma unroll 8
        for (int k = 0; k < 128; k++) a = fmaf(h1[k], wrow[k], a);
        h2[j] = fmaxf(a, 0.f);
    }
    __syncthreads();
    if (j < 64) {
        float p = h2[j] * f3w[j];
        p += __shfl_xor_sync(0xffffffffu, p, 16);
        p += __shfl_xor_sync(0xffffffffu, p, 8);
        p += __shfl_xor_sync(0xffffffffu, p, 4);
        p += __shfl_xor_sync(0xffffffffu, p, 2);
        p += __shfl_xor_sync(0xffffffffu, p, 1);
        if ((j & 31) == 0) part[j >> 5] = p;
    }
    __syncthreads();
    if (j == 0) out[b] = part[0] + part[1] + f3b[0];
}

// ---------------------------------------------------------------------------
extern "C" void kernel_launch(void* const* d_in, const int* in_sizes, int n_in,
                              void* d_out, int out_size)
{
    const float* x        = (const float*)d_in[0];
    const float* Wp       = (const float*)d_in[1];
    const float* bp       = (const float*)d_in[2];
    const float* Wrec     = (const float*)d_in[3];
    const float* Win_w    = (const float*)d_in[4];
    const float* Win_b    = (const float*)d_in[5];
    const float* cbias    = (const float*)d_in[6];
    const float* tau_base = (const float*)d_in[7];
    const float* vg1_w    = (const float*)d_in[8];
    const float* vg1_b    = (const float*)d_in[9];
    const float* vg2_w    = (const float*)d_in[10];
    const float* vg2_b    = (const float*)d_in[11];
    const float* proj_w   = (const float*)d_in[12];
    const float* proj_b   = (const float*)d_in[13];
    const float* f1w      = (const float*)d_in[14];
    const float* f1b      = (const float*)d_in[15];
    const float* f2w      = (const float*)d_in[16];
    const float* f2b      = (const float*)d_in[17];
    const float* f3w      = (const float*)d_in[18];
    const float* f3b      = (const float*)d_in[19];
    float* out = (float*)d_out;

    cudaFuncSetAttribute(liquid_kernel,
                         cudaFuncAttributeMaxDynamicSharedMemorySize, SMEM_BYTES);

    xproj_kernel<<<(BB * TT) / 32, 128>>>(x, Wp, bp);
    liquid_kernel<<<148, 256, SMEM_BYTES>>>(Wrec, Win_w, Win_b, cbias, tau_base,
                                            vg1_w, vg1_b, vg2_w, vg2_b);
    head_kernel<<<BB, 128>>>(proj_w, proj_b, f1w, f1b, f2w, f2b, f3w, f3b, out);
}

// round 6
// speedup vs baseline: 1.4799x; 1.3057x over previous
#include <cuda_runtime.h>
#include <cuda_bf16.h>
#include <math.h>

#define BB   256
#define TT   512
#define HH   128
#define SS   4
#define DTC  0.1f

// device-global scratch (allocation-free)
__device__ float g_xproj[(size_t)BB * TT * HH];   // 64 MB, [b][t][h]
__device__ float g_hT[SS * BB * HH];

// ---- shared layout (float offsets) ----
#define OFF_WR   0            // 128*132, row-major [col][k], pad 132
#define OFF_WI   16896
#define OFF_V1   33792        // 32*132
#define OFF_V2   38016        // 128*36
#define OFF_BC   42624
#define OFF_V2B  42752
#define OFF_V1B  42880
#define OFF_GRP  42912
// per-group: sh 896 | sx 896 | sp 3584 | sqp 896 | sqs 224 | sred 32
#define GRP_STRIDE 6528
#define SMEM_FLOATS (OFF_GRP + 2 * GRP_STRIDE)
#define SMEM_BYTES  (SMEM_FLOATS * 4)   // 223872 B

__device__ __forceinline__ float fast_tanh(float x) {
    float ax = fminf(fabsf(x), 12.0f);
    float e  = __expf(2.0f * ax);
    float r  = __fdividef(e - 1.0f, e + 1.0f);
    return copysignf(r, x);
}

// ---------------------------------------------------------------------------
// K1: x_proj = x @ Wp^T + bp
// ---------------------------------------------------------------------------
__global__ __launch_bounds__(128) void xproj_kernel(
    const float* __restrict__ x, const float* __restrict__ Wp,
    const float* __restrict__ bp)
{
    __shared__ float sW[128 * 36];
    __shared__ float sx[32 * 32];
    __shared__ float sb[128];
    const int tid = threadIdx.x;

    for (int idx = tid; idx < 128 * 32; idx += 128) {
        int j = idx >> 5, k = idx & 31;
        sW[j * 36 + k] = Wp[idx];
    }
    sb[tid] = bp[tid];
    const size_t base = (size_t)blockIdx.x * 32;
    for (int idx = tid; idx < 1024; idx += 128)
        sx[idx] = x[base * 32 + idx];
    __syncthreads();

    float acc[32];
    const float b = sb[tid];
    #pragma unroll
    for (int r = 0; r < 32; r++) acc[r] = b;

    #pragma unroll 2
    for (int kk = 0; kk < 32; kk += 4) {
        const float4 w4 = *(const float4*)&sW[tid * 36 + kk];
        #pragma unroll
        for (int r = 0; r < 32; r++) {
            const float4 x4 = *(const float4*)&sx[r * 32 + kk];
            acc[r] = fmaf(x4.x, w4.x, acc[r]);
            acc[r] = fmaf(x4.y, w4.y, acc[r]);
            acc[r] = fmaf(x4.z, w4.z, acc[r]);
            acc[r] = fmaf(x4.w, w4.w, acc[r]);
        }
    }
    #pragma unroll
    for (int r = 0; r < 32; r++)
        g_xproj[(base + r) * HH + tid] = acc[r];
}

// ---------------------------------------------------------------------------
// k-split partial GEMM: thread (w,l) computes cols {l+32i} over k in
// [32w,32w+32) for G rows from vec[r*128+k], weights W[col*132+k] (SMEM).
// Partials land in sp[(r*4+w)*128 + col].
// ---------------------------------------------------------------------------
template<int G>
__device__ __forceinline__ void partial_gemm(
    const float* __restrict__ sW, const float* __restrict__ svec,
    float* __restrict__ sp, int w, int l)
{
    float acc[4][G];
    #pragma unroll
    for (int i = 0; i < 4; i++)
        #pragma unroll
        for (int r = 0; r < G; r++) acc[i][r] = 0.f;

    const int k0 = 32 * w;
    #pragma unroll
    for (int kk = 0; kk < 8; kk++) {
        float4 w4[4];
        #pragma unroll
        for (int i = 0; i < 4; i++)
            w4[i] = *(const float4*)&sW[(l + 32 * i) * 132 + k0 + 4 * kk];
        #pragma unroll
        for (int r = 0; r < G; r++) {
            const float4 x4 = *(const float4*)&svec[r * 128 + k0 + 4 * kk];
            #pragma unroll
            for (int i = 0; i < 4; i++) {
                acc[i][r] = fmaf(w4[i].x, x4.x, acc[i][r]);
                acc[i][r] = fmaf(w4[i].y, x4.y, acc[i][r]);
                acc[i][r] = fmaf(w4[i].z, x4.z, acc[i][r]);
                acc[i][r] = fmaf(w4[i].w, x4.w, acc[i][r]);
            }
        }
    }
    #pragma unroll
    for (int r = 0; r < G; r++)
        #pragma unroll
        for (int i = 0; i < 4; i++)
            sp[(r * 4 + w) * 128 + l + 32 * i] = acc[i][r];
}

// ---------------------------------------------------------------------------
// K2: persistent liquid recurrence. 256 threads = 2 independent 128-thread
// groups (named barriers) sharing one SMEM weight copy.
// ---------------------------------------------------------------------------
template<int G, int NS>
__device__ __forceinline__ void run_group(
    const float* __restrict__ tau_base, int s, int grow0)
{
    extern __shared__ float sm[];
    const int tid  = threadIdx.x;
    const int g    = tid >> 7;
    const int gtid = tid & 127;
    const int w = gtid >> 5, l = gtid & 31;

    float* gs   = sm + OFF_GRP + g * GRP_STRIDE;
    float* sh   = gs;
    float* sx   = gs + 896;
    float* sp   = gs + 1792;
    float* sqp  = gs + 5376;
    float* sqs  = gs + 6272;
    float* sred = gs + 6496;
    const float* sWr  = sm + OFF_WR;
    const float* sWi  = sm + OFF_WI;
    const float* sV1  = sm + OFF_V1;
    const float* sV2  = sm + OFF_V2;
    const float* sbc  = sm + OFF_BC;
    const float* sv2b = sm + OFF_V2B;
    const float* sv1b = sm + OFF_V1B;

    const int barid = g + 1;
    #define GBAR() asm volatile("bar.sync %0, 128;" :: "r"(barid) : "memory")

    const float tb = tau_base[s * 128 + gtid];
    float hj[G], xreg[G];
    int xoff[G];
    #pragma unroll
    for (int r = 0; r < G; r++) {
        hj[r] = 0.f;
        sh[r * 128 + gtid] = 0.f;
        const int row = min(grow0 + r, BB - 1);
        xoff[r] = row * (TT * HH);
        xreg[r] = g_xproj[xoff[r] + gtid];
    }
    GBAR();

    for (int t = 0; t < TT; t++) {
        #pragma unroll
        for (int r = 0; r < G; r++) sx[r * 128 + gtid] = xreg[r];
        GBAR();

        // ---- gate layer 1 partials: thread l = gate row, k-chunk w ----
        {
            float qp[G];
            #pragma unroll
            for (int r = 0; r < G; r++) qp[r] = 0.f;
            const int k0 = w * 32;
            #pragma unroll
            for (int kk = 0; kk < 32; kk += 4) {
                const float4 v4 = *(const float4*)&sV1[l * 132 + k0 + kk];
                #pragma unroll
                for (int r = 0; r < G; r++) {
                    const float4 x4 = *(const float4*)&sx[r * 128 + k0 + kk];
                    qp[r] = fmaf(x4.x, v4.x, qp[r]);
                    qp[r] = fmaf(x4.y, v4.y, qp[r]);
                    qp[r] = fmaf(x4.z, v4.z, qp[r]);
                    qp[r] = fmaf(x4.w, v4.w, qp[r]);
                }
            }
            #pragma unroll
            for (int r = 0; r < G; r++) sqp[w * 224 + r * 32 + l] = qp[r];
        }
        GBAR();
        if (gtid < 32) {
            #pragma unroll
            for (int r = 0; r < G; r++) {
                float q = sqp[r * 32 + gtid] + sqp[224 + r * 32 + gtid]
                        + sqp[448 + r * 32 + gtid] + sqp[672 + r * 32 + gtid]
                        + sv1b[gtid];
                sqs[r * 32 + gtid] = fmaxf(q, 0.f);
            }
        }
        GBAR();

        // ---- gate layer 2 -> rtau (owner column gtid) ----
        float rtau[G];
        {
            float va[G];
            #pragma unroll
            for (int r = 0; r < G; r++) va[r] = sv2b[gtid];
            #pragma unroll
            for (int ii = 0; ii < 32; ii += 4) {
                const float4 w4 = *(const float4*)&sV2[gtid * 36 + ii];
                #pragma unroll
                for (int r = 0; r < G; r++) {
                    const float4 q4 = *(const float4*)&sqs[r * 32 + ii];
                    va[r] = fmaf(q4.x, w4.x, va[r]);
                    va[r] = fmaf(q4.y, w4.y, va[r]);
                    va[r] = fmaf(q4.z, w4.z, va[r]);
                    va[r] = fmaf(q4.w, w4.w, va[r]);
                }
            }
            #pragma unroll
            for (int r = 0; r < G; r++) {
                const float vol = __fdividef(1.f, 1.f + __expf(-va[r]));
                float ta = tb * (0.2f + 1.8f * (1.f - vol));
                ta = fminf(fmaxf(ta, 0.1f), 10.f);
                rtau[r] = __frcp_rn(ta);
            }
        }

        // ---- inp = x @ Wi^T + bc : partials then combine ----
        partial_gemm<G>(sWi, sx, sp, w, l);
        GBAR();
        float inp[G];
        #pragma unroll
        for (int r = 0; r < G; r++)
            inp[r] = sp[(r * 4 + 0) * 128 + gtid] + sp[(r * 4 + 1) * 128 + gtid]
                   + sp[(r * 4 + 2) * 128 + gtid] + sp[(r * 4 + 3) * 128 + gtid]
                   + sbc[gtid];

        // prefetch next timestep x (L2 hit; hidden behind inner steps)
        if (t + 1 < TT) {
            #pragma unroll
            for (int r = 0; r < G; r++)
                xreg[r] = g_xproj[xoff[r] + (t + 1) * 128 + gtid];
        }

        // ---- inner ODE steps ----
        #pragma unroll 1
        for (int it = 0; it < NS; it++) {
            GBAR();   // sp consumed by all before overwrite
            partial_gemm<G>(sWr, sh, sp, w, l);
            GBAR();

            float d[G];
            #pragma unroll
            for (int r = 0; r < G; r++) {
                const float pre = sp[(r * 4 + 0) * 128 + gtid] + sp[(r * 4 + 1) * 128 + gtid]
                                + sp[(r * 4 + 2) * 128 + gtid] + sp[(r * 4 + 3) * 128 + gtid]
                                + inp[r];
                d[r] = (fast_tanh(pre) - hj[r]) * rtau[r];
            }
            #pragma unroll
            for (int r = 0; r < G; r++) {
                float sq = d[r] * d[r];
                sq += __shfl_xor_sync(0xffffffffu, sq, 16);
                sq += __shfl_xor_sync(0xffffffffu, sq, 8);
                sq += __shfl_xor_sync(0xffffffffu, sq, 4);
                sq += __shfl_xor_sync(0xffffffffu, sq, 2);
                sq += __shfl_xor_sync(0xffffffffu, sq, 1);
                if (l == 0) sred[r * 4 + w] = sq;
            }
            GBAR();
            #pragma unroll
            for (int r = 0; r < G; r++) {
                const float4 s4 = *(const float4*)&sred[r * 4];
                const float mag = sqrtf(s4.x + s4.y + s4.z + s4.w);
                const float coef = __fdividef(DTC, 1.f + 0.2f * mag);
                hj[r] = fmaf(coef, d[r], hj[r]);
                sh[r * 128 + gtid] = hj[r];
            }
            GBAR();   // sh visible before next partial pass
        }
    }

    #pragma unroll
    for (int r = 0; r < G; r++) {
        const int row = min(grow0 + r, BB - 1);
        g_hT[(s * BB + row) * HH + gtid] = hj[r];
    }
    #undef GBAR
}

__global__ __launch_bounds__(256, 1) void liquid_kernel(
    const float* __restrict__ Wrec, const float* __restrict__ Win_w,
    const float* __restrict__ Win_b, const float* __restrict__ cbias,
    const float* __restrict__ tau_base,
    const float* __restrict__ v1w, const float* __restrict__ v1b,
    const float* __restrict__ v2w, const float* __restrict__ v2b)
{
    extern __shared__ float sm[];
    const int tid = threadIdx.x;
    const int b = blockIdx.x;

    int s, row0;
    if      (b < 21) { s = 0; row0 = b * 13; }
    else if (b < 53) { s = 1; row0 = (b - 21) * 8; }
    else if (b < 96) { s = 2; row0 = (b - 53) * 6; }
    else             { s = 3; row0 = (b - 96) * 5; }

    const float* Wr = Wrec  + s * 16384;
    const float* Wi = Win_w + s * 16384;
    for (int idx = tid; idx < 16384; idx += 256) {
        int j = idx >> 7, k = idx & 127;
        sm[OFF_WR + j * 132 + k] = Wr[idx];
        sm[OFF_WI + j * 132 + k] = Wi[idx];
    }
    for (int idx = tid; idx < 32 * 128; idx += 256) {
        int j = idx >> 7, k = idx & 127;
        sm[OFF_V1 + j * 132 + k] = v1w[s * 4096 + idx];
    }
    for (int idx = tid; idx < 128 * 32; idx += 256) {
        int j = idx >> 5, k = idx & 31;
        sm[OFF_V2 + j * 36 + k] = v2w[s * 4096 + idx];
    }
    if (tid < 128) {
        sm[OFF_BC  + tid] = Win_b[s * 128 + tid] + cbias[s * 128 + tid];
        sm[OFF_V2B + tid] = v2b[s * 128 + tid];
        if (tid < 32) sm[OFF_V1B + tid] = v1b[s * 32 + tid];
    }
    __syncthreads();

    const int g = tid >> 7;
    if      (b < 21) { if (!g) run_group<7, 3>(tau_base, 0, row0);
                       else    run_group<6, 3>(tau_base, 0, row0 + 7); }
    else if (b < 53) {          run_group<4, 5>(tau_base, 1, row0 + g * 4); }
    else if (b < 96) {          run_group<3, 7>(tau_base, 2, row0 + g * 3); }
    else             { if (!g) run_group<3, 9>(tau_base, 3, row0);
                       else    run_group<2, 9>(tau_base, 3, row0 + 3); }
}

// ---------------------------------------------------------------------------
// K3: projection + concat + fusion MLP. One block per batch row.
// ---------------------------------------------------------------------------
__global__ __launch_bounds__(128) void head_kernel(
    const float* __restrict__ proj_w, const float* __restrict__ proj_b,
    const float* __restrict__ f1w, const float* __restrict__ f1b,
    const float* __restrict__ f2w, const float* __restrict__ f2b,
    const float* __restrict__ f3w, const float* __restrict__ f3b,
    float* __restrict__ out)
{
    __shared__ float fused[128];
    __shared__ float h1[128];
    __shared__ float h2[64];
    __shared__ float part[2];
    const int b = blockIdx.x;
    const int j = threadIdx.x;
    const int s = j >> 5, i = j & 31;

    {
        const float* h  = &g_hT[(s * BB + b) * HH];
        const float* pw = &proj_w[(s * 32 + i) * HH];
        float a = proj_b[s * 32 + i];
        #pragma unroll 8
        for (int k = 0; k < 128; k++) a = fmaf(h[k], pw[k], a);
        fused[j] = a;
    }
    __syncthreads();
    {
        float a = f1b[j];
        const float* wrow = &f1w[j * 128];
        #pragma unroll 8
        for (int k = 0; k < 128; k++) a = fmaf(fused[k], wrow[k], a);
        h1[j] = fmaxf(a, 0.f);
    }
    __syncthreads();
    if (j < 64) {
        float a = f2b[j];
        const float* wrow = &f2w[j * 128];
        #pragma unroll 8
        for (int k = 0; k < 128; k++) a = fmaf(h1[k], wrow[k], a);
        h2[j] = fmaxf(a, 0.f);
    }
    __syncthreads();
    if (j < 64) {
        float p = h2[j] * f3w[j];
        p += __shfl_xor_sync(0xffffffffu, p, 16);
        p += __shfl_xor_sync(0xffffffffu, p, 8);
        p += __shfl_xor_sync(0xffffffffu, p, 4);
        p += __shfl_xor_sync(0xffffffffu, p, 2);
        p += __shfl_xor_sync(0xffffffffu, p, 1);
        if ((j & 31) == 0) part[j >> 5] = p;
    }
    __syncthreads();
    if (j == 0) out[b] = part[0] + part[1] + f3b[0];
}

// ---------------------------------------------------------------------------
extern "C" void kernel_launch(void* const* d_in, const int* in_sizes, int n_in,
                              void* d_out, int out_size)
{
    const float* x        = (const float*)d_in[0];
    const float* Wp       = (const float*)d_in[1];
    const float* bp       = (const float*)d_in[2];
    const float* Wrec     = (const float*)d_in[3];
    const float* Win_w    = (const float*)d_in[4];
    const float* Win_b    = (const float*)d_in[5];
    const float* cbias    = (const float*)d_in[6];
    const float* tau_base = (const float*)d_in[7];
    const float* vg1_w    = (const float*)d_in[8];
    const float* vg1_b    = (const float*)d_in[9];
    const float* vg2_w    = (const float*)d_in[10];
    const float* vg2_b    = (const float*)d_in[11];
    const float* proj_w   = (const float*)d_in[12];
    const float* proj_b   = (const float*)d_in[13];
    const float* f1w      = (const float*)d_in[14];
    const float* f1b      = (const float*)d_in[15];
    const float* f2w      = (const float*)d_in[16];
    const float* f2b      = (const float*)d_in[17];
    const float* f3w      = (const float*)d_in[18];
    const float* f3b      = (const float*)d_in[19];
    float* out = (float*)d_out;

    cudaFuncSetAttribute(liquid_kernel,
                         cudaFuncAttributeMaxDynamicSharedMemorySize, SMEM_BYTES);

    xproj_kernel<<<(BB * TT) / 32, 128>>>(x, Wp, bp);
    liquid_kernel<<<148, 256, SMEM_BYTES>>>(Wrec, Win_w, Win_b, cbias, tau_base,
                                            vg1_w, vg1_b, vg2_w, vg2_b);
    head_kernel<<<BB, 128>>>(proj_w, proj_b, f1w, f1b, f2w, f2b, f3w, f3b, out);
}

// round 7
// speedup vs baseline: 1.5074x; 1.0186x over previous
#include <cuda_runtime.h>
#include <cuda_bf16.h>
#include <math.h>

#define BB   256
#define TT   512
#define HH   128
#define SS   4
#define DTC  0.1f

// device-global scratch (allocation-free)
__device__ float g_xproj[(size_t)BB * TT * HH];   // 64 MB, [b][t][h]
__device__ float g_hT[SS * BB * HH];

// ---- shared layout (float offsets) ----
#define OFF_WR   0            // 128*128 TRANSPOSED: [k][col]
#define OFF_WI   16384        // 128*128 TRANSPOSED: [k][col]
#define OFF_V1   32768        // 32*132
#define OFF_V2   36992        // 128*36
#define OFF_BC   41600
#define OFF_V2B  41728
#define OFF_V1B  41856
#define OFF_GRP  41888
// per-group: sh 896 | sx 896 | sp 3584 | sqp 896 | sqs 224 | sred 32
#define GRP_STRIDE 6528
#define SMEM_FLOATS (OFF_GRP + 2 * GRP_STRIDE)
#define SMEM_BYTES  (SMEM_FLOATS * 4)   // 219776 B

__device__ __forceinline__ float fast_tanh(float x) {
    float ax = fminf(fabsf(x), 12.0f);
    float e  = __expf(2.0f * ax);
    float r  = __fdividef(e - 1.0f, e + 1.0f);
    return copysignf(r, x);
}

// ---------------------------------------------------------------------------
// K1: x_proj = x @ Wp^T + bp
// ---------------------------------------------------------------------------
__global__ __launch_bounds__(128) void xproj_kernel(
    const float* __restrict__ x, const float* __restrict__ Wp,
    const float* __restrict__ bp)
{
    __shared__ float sW[128 * 36];
    __shared__ float sx[32 * 32];
    __shared__ float sb[128];
    const int tid = threadIdx.x;

    for (int idx = tid; idx < 128 * 32; idx += 128) {
        int j = idx >> 5, k = idx & 31;
        sW[j * 36 + k] = Wp[idx];
    }
    sb[tid] = bp[tid];
    const size_t base = (size_t)blockIdx.x * 32;
    for (int idx = tid; idx < 1024; idx += 128)
        sx[idx] = x[base * 32 + idx];
    __syncthreads();

    float acc[32];
    const float b = sb[tid];
    #pragma unroll
    for (int r = 0; r < 32; r++) acc[r] = b;

    #pragma unroll 2
    for (int kk = 0; kk < 32; kk += 4) {
        const float4 w4 = *(const float4*)&sW[tid * 36 + kk];
        #pragma unroll
        for (int r = 0; r < 32; r++) {
            const float4 x4 = *(const float4*)&sx[r * 32 + kk];
            acc[r] = fmaf(x4.x, w4.x, acc[r]);
            acc[r] = fmaf(x4.y, w4.y, acc[r]);
            acc[r] = fmaf(x4.z, w4.z, acc[r]);
            acc[r] = fmaf(x4.w, w4.w, acc[r]);
        }
    }
    #pragma unroll
    for (int r = 0; r < 32; r++)
        g_xproj[(base + r) * HH + tid] = acc[r];
}

// ---------------------------------------------------------------------------
// k-split partial GEMM, transposed weights (conflict-free).
// Thread (w,l) owns cols 4l..4l+3 over k in [32w,32w+32) for G rows.
// sWT[k*128 + col]; partials -> sp[(r*4+w)*128 + col].
// ---------------------------------------------------------------------------
template<int G>
__device__ __forceinline__ void partial_gemm_T(
    const float* __restrict__ sWT, const float* __restrict__ svec,
    float* __restrict__ sp, int w, int l)
{
    float4 acc[G];
    #pragma unroll
    for (int r = 0; r < G; r++) acc[r] = make_float4(0.f, 0.f, 0.f, 0.f);

    const int k0 = 32 * w;
    const int c0 = 4 * l;
    #pragma unroll
    for (int kk = 0; kk < 8; kk++) {
        const float4 w0 = *(const float4*)&sWT[(k0 + 4 * kk + 0) * 128 + c0];
        const float4 w1 = *(const float4*)&sWT[(k0 + 4 * kk + 1) * 128 + c0];
        const float4 w2 = *(const float4*)&sWT[(k0 + 4 * kk + 2) * 128 + c0];
        const float4 w3 = *(const float4*)&sWT[(k0 + 4 * kk + 3) * 128 + c0];
        #pragma unroll
        for (int r = 0; r < G; r++) {
            const float4 x4 = *(const float4*)&svec[r * 128 + k0 + 4 * kk];
            acc[r].x = fmaf(w0.x, x4.x, acc[r].x);
            acc[r].y = fmaf(w0.y, x4.x, acc[r].y);
            acc[r].z = fmaf(w0.z, x4.x, acc[r].z);
            acc[r].w = fmaf(w0.w, x4.x, acc[r].w);
            acc[r].x = fmaf(w1.x, x4.y, acc[r].x);
            acc[r].y = fmaf(w1.y, x4.y, acc[r].y);
            acc[r].z = fmaf(w1.z, x4.y, acc[r].z);
            acc[r].w = fmaf(w1.w, x4.y, acc[r].w);
            acc[r].x = fmaf(w2.x, x4.z, acc[r].x);
            acc[r].y = fmaf(w2.y, x4.z, acc[r].y);
            acc[r].z = fmaf(w2.z, x4.z, acc[r].z);
            acc[r].w = fmaf(w2.w, x4.z, acc[r].w);
            acc[r].x = fmaf(w3.x, x4.w, acc[r].x);
            acc[r].y = fmaf(w3.y, x4.w, acc[r].y);
            acc[r].z = fmaf(w3.z, x4.w, acc[r].z);
            acc[r].w = fmaf(w3.w, x4.w, acc[r].w);
        }
    }
    #pragma unroll
    for (int r = 0; r < G; r++)
        *(float4*)&sp[(r * 4 + w) * 128 + c0] = acc[r];
}

// ---------------------------------------------------------------------------
// K2: persistent liquid recurrence. 256 threads = 2 independent 128-thread
// groups (named barriers) sharing one SMEM weight copy.
// ---------------------------------------------------------------------------
template<int G, int NS>
__device__ __forceinline__ void run_group(
    const float* __restrict__ tau_base, int s, int grow0)
{
    extern __shared__ float sm[];
    const int tid  = threadIdx.x;
    const int g    = tid >> 7;
    const int gtid = tid & 127;
    const int w = gtid >> 5, l = gtid & 31;

    float* gs   = sm + OFF_GRP + g * GRP_STRIDE;
    float* sh   = gs;
    float* sx   = gs + 896;
    float* sp   = gs + 1792;
    float* sqp  = gs + 5376;
    float* sqs  = gs + 6272;
    float* sred = gs + 6496;
    const float* sWr  = sm + OFF_WR;
    const float* sWi  = sm + OFF_WI;
    const float* sV1  = sm + OFF_V1;
    const float* sV2  = sm + OFF_V2;
    const float* sbc  = sm + OFF_BC;
    const float* sv2b = sm + OFF_V2B;
    const float* sv1b = sm + OFF_V1B;

    const int barid = g + 1;
    #define GBAR() asm volatile("bar.sync %0, 128;" :: "r"(barid) : "memory")

    const float tb = tau_base[s * 128 + gtid];
    float hj[G], xreg[G];
    int xoff[G];
    #pragma unroll
    for (int r = 0; r < G; r++) {
        hj[r] = 0.f;
        sh[r * 128 + gtid] = 0.f;
        const int row = min(grow0 + r, BB - 1);
        xoff[r] = row * (TT * HH);
        xreg[r] = g_xproj[xoff[r] + gtid];
    }
    GBAR();

    for (int t = 0; t < TT; t++) {
        #pragma unroll
        for (int r = 0; r < G; r++) sx[r * 128 + gtid] = xreg[r];
        GBAR();

        // ---- gate layer 1 partials: thread l = gate row, k-chunk w ----
        {
            float qp[G];
            #pragma unroll
            for (int r = 0; r < G; r++) qp[r] = 0.f;
            const int k0 = w * 32;
            #pragma unroll
            for (int kk = 0; kk < 32; kk += 4) {
                const float4 v4 = *(const float4*)&sV1[l * 132 + k0 + kk];
                #pragma unroll
                for (int r = 0; r < G; r++) {
                    const float4 x4 = *(const float4*)&sx[r * 128 + k0 + kk];
                    qp[r] = fmaf(x4.x, v4.x, qp[r]);
                    qp[r] = fmaf(x4.y, v4.y, qp[r]);
                    qp[r] = fmaf(x4.z, v4.z, qp[r]);
                    qp[r] = fmaf(x4.w, v4.w, qp[r]);
                }
            }
            #pragma unroll
            for (int r = 0; r < G; r++) sqp[w * 224 + r * 32 + l] = qp[r];
        }
        GBAR();
        if (gtid < 32) {
            #pragma unroll
            for (int r = 0; r < G; r++) {
                float q = sqp[r * 32 + gtid] + sqp[224 + r * 32 + gtid]
                        + sqp[448 + r * 32 + gtid] + sqp[672 + r * 32 + gtid]
                        + sv1b[gtid];
                sqs[r * 32 + gtid] = fmaxf(q, 0.f);
            }
        }
        GBAR();

        // ---- gate layer 2 -> rtau (owner column gtid) ----
        float rtau[G];
        {
            float va[G];
            #pragma unroll
            for (int r = 0; r < G; r++) va[r] = sv2b[gtid];
            #pragma unroll
            for (int ii = 0; ii < 32; ii += 4) {
                const float4 w4 = *(const float4*)&sV2[gtid * 36 + ii];
                #pragma unroll
                for (int r = 0; r < G; r++) {
                    const float4 q4 = *(const float4*)&sqs[r * 32 + ii];
                    va[r] = fmaf(q4.x, w4.x, va[r]);
                    va[r] = fmaf(q4.y, w4.y, va[r]);
                    va[r] = fmaf(q4.z, w4.z, va[r]);
                    va[r] = fmaf(q4.w, w4.w, va[r]);
                }
            }
            #pragma unroll
            for (int r = 0; r < G; r++) {
                const float vol = __fdividef(1.f, 1.f + __expf(-va[r]));
                float ta = tb * (0.2f + 1.8f * (1.f - vol));
                ta = fminf(fmaxf(ta, 0.1f), 10.f);
                rtau[r] = __frcp_rn(ta);
            }
        }

        // ---- inp = x @ Wi^T + bc : partials then combine ----
        partial_gemm_T<G>(sWi, sx, sp, w, l);
        GBAR();
        float inp[G];
        #pragma unroll
        for (int r = 0; r < G; r++)
            inp[r] = sp[(r * 4 + 0) * 128 + gtid] + sp[(r * 4 + 1) * 128 + gtid]
                   + sp[(r * 4 + 2) * 128 + gtid] + sp[(r * 4 + 3) * 128 + gtid]
                   + sbc[gtid];

        // prefetch next timestep x (L2 hit; hidden behind inner steps)
        if (t + 1 < TT) {
            #pragma unroll
            for (int r = 0; r < G; r++)
                xreg[r] = g_xproj[xoff[r] + (t + 1) * 128 + gtid];
        }
        GBAR();   // all inp-combine reads of sp done before first inner overwrite

        // ---- inner ODE steps: 3 barriers per step ----
        #pragma unroll 1
        for (int it = 0; it < NS; it++) {
            partial_gemm_T<G>(sWr, sh, sp, w, l);
            GBAR();

            float d[G];
            #pragma unroll
            for (int r = 0; r < G; r++) {
                const float pre = sp[(r * 4 + 0) * 128 + gtid] + sp[(r * 4 + 1) * 128 + gtid]
                                + sp[(r * 4 + 2) * 128 + gtid] + sp[(r * 4 + 3) * 128 + gtid]
                                + inp[r];
                d[r] = (fast_tanh(pre) - hj[r]) * rtau[r];
            }
            #pragma unroll
            for (int r = 0; r < G; r++) {
                float sq = d[r] * d[r];
                sq += __shfl_xor_sync(0xffffffffu, sq, 16);
                sq += __shfl_xor_sync(0xffffffffu, sq, 8);
                sq += __shfl_xor_sync(0xffffffffu, sq, 4);
                sq += __shfl_xor_sync(0xffffffffu, sq, 2);
                sq += __shfl_xor_sync(0xffffffffu, sq, 1);
                if (l == 0) sred[r * 4 + w] = sq;
            }
            GBAR();
            #pragma unroll
            for (int r = 0; r < G; r++) {
                const float4 s4 = *(const float4*)&sred[r * 4];
                const float mag = sqrtf(s4.x + s4.y + s4.z + s4.w);
                const float coef = __fdividef(DTC, 1.f + 0.2f * mag);
                hj[r] = fmaf(coef, d[r], hj[r]);
                sh[r * 128 + gtid] = hj[r];
            }
            GBAR();   // sh visible (and sp free) before next pass
        }
    }

    #pragma unroll
    for (int r = 0; r < G; r++) {
        const int row = min(grow0 + r, BB - 1);
        g_hT[(s * BB + row) * HH + gtid] = hj[r];
    }
    #undef GBAR
}

__global__ __launch_bounds__(256, 1) void liquid_kernel(
    const float* __restrict__ Wrec, const float* __restrict__ Win_w,
    const float* __restrict__ Win_b, const float* __restrict__ cbias,
    const float* __restrict__ tau_base,
    const float* __restrict__ v1w, const float* __restrict__ v1b,
    const float* __restrict__ v2w, const float* __restrict__ v2b)
{
    extern __shared__ float sm[];
    const int tid = threadIdx.x;
    const int b = blockIdx.x;

    int s, row0;
    if      (b < 21) { s = 0; row0 = b * 13; }
    else if (b < 53) { s = 1; row0 = (b - 21) * 8; }
    else if (b < 96) { s = 2; row0 = (b - 53) * 6; }
    else             { s = 3; row0 = (b - 96) * 5; }

    // stage weights TRANSPOSED: sWT[k*128 + col] = W[col*128 + k]
    // (one-time uncoalesced GMEM read; conflict-free use for 512 timesteps)
    const float* Wr = Wrec  + s * 16384;
    const float* Wi = Win_w + s * 16384;
    for (int idx = tid; idx < 16384; idx += 256) {
        const int k = idx >> 7, c = idx & 127;
        sm[OFF_WR + idx] = Wr[c * 128 + k];
        sm[OFF_WI + idx] = Wi[c * 128 + k];
    }
    for (int idx = tid; idx < 32 * 128; idx += 256) {
        int j = idx >> 7, k = idx & 127;
        sm[OFF_V1 + j * 132 + k] = v1w[s * 4096 + idx];
    }
    for (int idx = tid; idx < 128 * 32; idx += 256) {
        int j = idx >> 5, k = idx & 31;
        sm[OFF_V2 + j * 36 + k] = v2w[s * 4096 + idx];
    }
    if (tid < 128) {
        sm[OFF_BC  + tid] = Win_b[s * 128 + tid] + cbias[s * 128 + tid];
        sm[OFF_V2B + tid] = v2b[s * 128 + tid];
        if (tid < 32) sm[OFF_V1B + tid] = v1b[s * 32 + tid];
    }
    __syncthreads();

    const int g = tid >> 7;
    if      (b < 21) { if (!g) run_group<7, 3>(tau_base, 0, row0);
                       else    run_group<6, 3>(tau_base, 0, row0 + 7); }
    else if (b < 53) {          run_group<4, 5>(tau_base, 1, row0 + g * 4); }
    else if (b < 96) {          run_group<3, 7>(tau_base, 2, row0 + g * 3); }
    else             { if (!g) run_group<3, 9>(tau_base, 3, row0);
                       else    run_group<2, 9>(tau_base, 3, row0 + 3); }
}

// ---------------------------------------------------------------------------
// K3: projection + concat + fusion MLP. One block per batch row.
// ---------------------------------------------------------------------------
__global__ __launch_bounds__(128) void head_kernel(
    const float* __restrict__ proj_w, const float* __restrict__ proj_b,
    const float* __restrict__ f1w, const float* __restrict__ f1b,
    const float* __restrict__ f2w, const float* __restrict__ f2b,
    const float* __restrict__ f3w, const float* __restrict__ f3b,
    float* __restrict__ out)
{
    __shared__ float fused[128];
    __shared__ float h1[128];
    __shared__ float h2[64];
    __shared__ float part[2];
    const int b = blockIdx.x;
    const int j = threadIdx.x;
    const int s = j >> 5, i = j & 31;

    {
        const float* h  = &g_hT[(s * BB + b) * HH];
        const float* pw = &proj_w[(s * 32 + i) * HH];
        float a = proj_b[s * 32 + i];
        #pragma unroll 8
        for (int k = 0; k < 128; k++) a = fmaf(h[k], pw[k], a);
        fused[j] = a;
    }
    __syncthreads();
    {
        float a = f1b[j];
        const float* wrow = &f1w[j * 128];
        #pragma unroll 8
        for (int k = 0; k < 128; k++) a = fmaf(fused[k], wrow[k], a);
        h1[j] = fmaxf(a, 0.f);
    }
    __syncthreads();
    if (j < 64) {
        float a = f2b[j];
        const float* wrow = &f2w[j * 128];
        #pragma unroll 8
        for (int k = 0; k < 128; k++) a = fmaf(h1[k], wrow[k], a);
        h2[j] = fmaxf(a, 0.f);
    }
    __syncthreads();
    if (j < 64) {
        float p = h2[j] * f3w[j];
        p += __shfl_xor_sync(0xffffffffu, p, 16);
        p += __shfl_xor_sync(0xffffffffu, p, 8);
        p += __shfl_xor_sync(0xffffffffu, p, 4);
        p += __shfl_xor_sync(0xffffffffu, p, 2);
        p += __shfl_xor_sync(0xffffffffu, p, 1);
        if ((j & 31) == 0) part[j >> 5] = p;
    }
    __syncthreads();
    if (j == 0) out[b] = part[0] + part[1] + f3b[0];
}

// ---------------------------------------------------------------------------
extern "C" void kernel_launch(void* const* d_in, const int* in_sizes, int n_in,
                              void* d_out, int out_size)
{
    const float* x        = (const float*)d_in[0];
    const float* Wp       = (const float*)d_in[1];
    const float* bp       = (const float*)d_in[2];
    const float* Wrec     = (const float*)d_in[3];
    const float* Win_w    = (const float*)d_in[4];
    const float* Win_b    = (const float*)d_in[5];
    const float* cbias    = (const float*)d_in[6];
    const float* tau_base = (const float*)d_in[7];
    const float* vg1_w    = (const float*)d_in[8];
    const float* vg1_b    = (const float*)d_in[9];
    const float* vg2_w    = (const float*)d_in[10];
    const float* vg2_b    = (const float*)d_in[11];
    const float* proj_w   = (const float*)d_in[12];
    const float* proj_b   = (const float*)d_in[13];
    const float* f1w      = (const float*)d_in[14];
    const float* f1b      = (const float*)d_in[15];
    const float* f2w      = (const float*)d_in[16];
    const float* f2b      = (const float*)d_in[17];
    const float* f3w      = (const float*)d_in[18];
    const float* f3b      = (const float*)d_in[19];
    float* out = (float*)d_out;

    cudaFuncSetAttribute(liquid_kernel,
                         cudaFuncAttributeMaxDynamicSharedMemorySize, SMEM_BYTES);

    xproj_kernel<<<(BB * TT) / 32, 128>>>(x, Wp, bp);
    liquid_kernel<<<148, 256, SMEM_BYTES>>>(Wrec, Win_w, Win_b, cbias, tau_base,
                                            vg1_w, vg1_b, vg2_w, vg2_b);
    head_kernel<<<BB, 128>>>(proj_w, proj_b, f1w, f1b, f2w, f2b, f3w, f3b, out);
}

// round 9
// speedup vs baseline: 1.5079x; 1.0003x over previous
#include <cuda_runtime.h>
#include <cuda_bf16.h>
#include <math.h>

#define BB   256
#define TT   512
#define HH   128
#define SS   4
#define DTC  0.1f

// device-global scratch (allocation-free)
__device__ float g_xproj[(size_t)BB * TT * HH];   // 64 MB, [b][t][h]
__device__ float g_hT[SS * BB * HH];

// ---- shared layout (float offsets) ----
#define OFF_WR   0            // 128*128 TRANSPOSED: [k][col]
#define OFF_WI   16384        // 128*128 TRANSPOSED: [k][col]
#define OFF_V1   32768        // 32*132
#define OFF_V2   36992        // 128*36
#define OFF_BC   41600
#define OFF_V2B  41728
#define OFF_V1B  41856
#define OFF_GRP  41888
// per-group: sh 896 | sx 896 | sp 3584 | sqp 896 | sqs 224 | sred 32
#define GRP_STRIDE 6528
#define SMEM_FLOATS (OFF_GRP + 2 * GRP_STRIDE)
#define SMEM_BYTES  (SMEM_FLOATS * 4)   // 219776 B

__device__ __forceinline__ float fast_tanh(float x) {
    float ax = fminf(fabsf(x), 12.0f);
    float e  = __expf(2.0f * ax);
    float r  = __fdividef(e - 1.0f, e + 1.0f);
    return copysignf(r, x);
}

// ---------------------------------------------------------------------------
// K1: x_proj = x @ Wp^T + bp
// ---------------------------------------------------------------------------
__global__ __launch_bounds__(128) void xproj_kernel(
    const float* __restrict__ x, const float* __restrict__ Wp,
    const float* __restrict__ bp)
{
    __shared__ float sW[128 * 36];
    __shared__ float sx[32 * 32];
    __shared__ float sb[128];
    const int tid = threadIdx.x;

    for (int idx = tid; idx < 128 * 32; idx += 128) {
        int j = idx >> 5, k = idx & 31;
        sW[j * 36 + k] = Wp[idx];
    }
    sb[tid] = bp[tid];
    const size_t base = (size_t)blockIdx.x * 32;
    for (int idx = tid; idx < 1024; idx += 128)
        sx[idx] = x[base * 32 + idx];
    __syncthreads();

    float acc[32];
    const float b = sb[tid];
    #pragma unroll
    for (int r = 0; r < 32; r++) acc[r] = b;

    #pragma unroll 2
    for (int kk = 0; kk < 32; kk += 4) {
        const float4 w4 = *(const float4*)&sW[tid * 36 + kk];
        #pragma unroll
        for (int r = 0; r < 32; r++) {
            const float4 x4 = *(const float4*)&sx[r * 32 + kk];
            acc[r] = fmaf(x4.x, w4.x, acc[r]);
            acc[r] = fmaf(x4.y, w4.y, acc[r]);
            acc[r] = fmaf(x4.z, w4.z, acc[r]);
            acc[r] = fmaf(x4.w, w4.w, acc[r]);
        }
    }
    #pragma unroll
    for (int r = 0; r < 32; r++)
        g_xproj[(base + r) * HH + tid] = acc[r];
}

// ---------------------------------------------------------------------------
// Packed-pair k-split partial GEMM (FFMA2 via fma.rn.f32x2).
// Thread (w,l) owns cols 4l..4l+3 (= 2 packed col-pairs) over k in
// [32w,32w+32) for G rows. sWT[k*128+col]; partials -> sp[(r*4+w)*128+col].
// Summation order per column identical to the scalar version.
// ---------------------------------------------------------------------------
template<int G>
__device__ __forceinline__ void partial_gemm_T2(
    const float* __restrict__ sWT, const float* __restrict__ svec,
    float* __restrict__ sp, int w, int l)
{
    unsigned long long accA[G], accB[G];
    #pragma unroll
    for (int r = 0; r < G; r++) { accA[r] = 0ull; accB[r] = 0ull; }

    const int k0 = 32 * w;
    const int c0 = 4 * l;
    #pragma unroll
    for (int kk = 0; kk < 8; kk++) {
        const ulonglong2 w0 = *(const ulonglong2*)&sWT[(k0 + 4 * kk + 0) * 128 + c0];
        const ulonglong2 w1 = *(const ulonglong2*)&sWT[(k0 + 4 * kk + 1) * 128 + c0];
        const ulonglong2 w2 = *(const ulonglong2*)&sWT[(k0 + 4 * kk + 2) * 128 + c0];
        const ulonglong2 w3 = *(const ulonglong2*)&sWT[(k0 + 4 * kk + 3) * 128 + c0];
        #pragma unroll
        for (int r = 0; r < G; r++) {
            const float4 x4 = *(const float4*)&svec[r * 128 + k0 + 4 * kk];
            unsigned long long px, py, pz, pw2;
            asm("mov.b64 %0, {%1, %1};" : "=l"(px)  : "f"(x4.x));
            asm("mov.b64 %0, {%1, %1};" : "=l"(py)  : "f"(x4.y));
            asm("mov.b64 %0, {%1, %1};" : "=l"(pz)  : "f"(x4.z));
            asm("mov.b64 %0, {%1, %1};" : "=l"(pw2) : "f"(x4.w));
            asm("fma.rn.f32x2 %0, %1, %2, %0;" : "+l"(accA[r]) : "l"(w0.x), "l"(px));
            asm("fma.rn.f32x2 %0, %1, %2, %0;" : "+l"(accB[r]) : "l"(w0.y), "l"(px));
            asm("fma.rn.f32x2 %0, %1, %2, %0;" : "+l"(accA[r]) : "l"(w1.x), "l"(py));
            asm("fma.rn.f32x2 %0, %1, %2, %0;" : "+l"(accB[r]) : "l"(w1.y), "l"(py));
            asm("fma.rn.f32x2 %0, %1, %2, %0;" : "+l"(accA[r]) : "l"(w2.x), "l"(pz));
            asm("fma.rn.f32x2 %0, %1, %2, %0;" : "+l"(accB[r]) : "l"(w2.y), "l"(pz));
            asm("fma.rn.f32x2 %0, %1, %2, %0;" : "+l"(accA[r]) : "l"(w3.x), "l"(pw2));
            asm("fma.rn.f32x2 %0, %1, %2, %0;" : "+l"(accB[r]) : "l"(w3.y), "l"(pw2));
        }
    }
    #pragma unroll
    for (int r = 0; r < G; r++) {
        ulonglong2 st;
        st.x = accA[r];
        st.y = accB[r];
        *(ulonglong2*)&sp[(r * 4 + w) * 128 + c0] = st;
    }
}

// ---------------------------------------------------------------------------
// K2: persistent liquid recurrence. 256 threads = 2 independent 128-thread
// groups (named barriers) sharing one SMEM weight copy.
// ---------------------------------------------------------------------------
template<int G, int NS>
__device__ __forceinline__ void run_group(
    const float* __restrict__ tau_base, int s, int grow0)
{
    extern __shared__ float sm[];
    const int tid  = threadIdx.x;
    const int g    = tid >> 7;
    const int gtid = tid & 127;
    const int w = gtid >> 5, l = gtid & 31;

    float* gs   = sm + OFF_GRP + g * GRP_STRIDE;
    float* sh   = gs;
    float* sx   = gs + 896;
    float* sp   = gs + 1792;
    float* sqp  = gs + 5376;
    float* sqs  = gs + 6272;
    float* sred = gs + 6496;
    const float* sWr  = sm + OFF_WR;
    const float* sWi  = sm + OFF_WI;
    const float* sV1  = sm + OFF_V1;
    const float* sV2  = sm + OFF_V2;
    const float* sbc  = sm + OFF_BC;
    const float* sv2b = sm + OFF_V2B;
    const float* sv1b = sm + OFF_V1B;

    const int barid = g + 1;
    #define GBAR() asm volatile("bar.sync %0, 128;" :: "r"(barid) : "memory")

    const float tb = tau_base[s * 128 + gtid];
    float hj[G], xreg[G];
    int xoff[G];
    #pragma unroll
    for (int r = 0; r < G; r++) {
        hj[r] = 0.f;
        sh[r * 128 + gtid] = 0.f;
        const int row = min(grow0 + r, BB - 1);
        xoff[r] = row * (TT * HH);
        xreg[r] = g_xproj[xoff[r] + gtid];
    }
    GBAR();

    for (int t = 0; t < TT; t++) {
        #pragma unroll
        for (int r = 0; r < G; r++) sx[r * 128 + gtid] = xreg[r];
        GBAR();

        // ---- gate layer 1 partials: thread l = gate row, k-chunk w ----
        {
            float qp[G];
            #pragma unroll
            for (int r = 0; r < G; r++) qp[r] = 0.f;
            const int k0 = w * 32;
            #pragma unroll
            for (int kk = 0; kk < 32; kk += 4) {
                const float4 v4 = *(const float4*)&sV1[l * 132 + k0 + kk];
                #pragma unroll
                for (int r = 0; r < G; r++) {
                    const float4 x4 = *(const float4*)&sx[r * 128 + k0 + kk];
                    qp[r] = fmaf(x4.x, v4.x, qp[r]);
                    qp[r] = fmaf(x4.y, v4.y, qp[r]);
                    qp[r] = fmaf(x4.z, v4.z, qp[r]);
                    qp[r] = fmaf(x4.w, v4.w, qp[r]);
                }
            }
            #pragma unroll
            for (int r = 0; r < G; r++) sqp[w * 224 + r * 32 + l] = qp[r];
        }
        GBAR();
        if (gtid < 32) {
            #pragma unroll
            for (int r = 0; r < G; r++) {
                float q = sqp[r * 32 + gtid] + sqp[224 + r * 32 + gtid]
                        + sqp[448 + r * 32 + gtid] + sqp[672 + r * 32 + gtid]
                        + sv1b[gtid];
                sqs[r * 32 + gtid] = fmaxf(q, 0.f);
            }
        }
        GBAR();

        // ---- gate layer 2 -> rtau (owner column gtid) ----
        float rtau[G];
        {
            float va[G];
            #pragma unroll
            for (int r = 0; r < G; r++) va[r] = sv2b[gtid];
            #pragma unroll
            for (int ii = 0; ii < 32; ii += 4) {
                const float4 w4 = *(const float4*)&sV2[gtid * 36 + ii];
                #pragma unroll
                for (int r = 0; r < G; r++) {
                    const float4 q4 = *(const float4*)&sqs[r * 32 + ii];
                    va[r] = fmaf(q4.x, w4.x, va[r]);
                    va[r] = fmaf(q4.y, w4.y, va[r]);
                    va[r] = fmaf(q4.z, w4.z, va[r]);
                    va[r] = fmaf(q4.w, w4.w, va[r]);
                }
            }
            #pragma unroll
            for (int r = 0; r < G; r++) {
                const float vol = __fdividef(1.f, 1.f + __expf(-va[r]));
                float ta = tb * (0.2f + 1.8f * (1.f - vol));
                ta = fminf(fmaxf(ta, 0.1f), 10.f);
                rtau[r] = __frcp_rn(ta);
            }
        }

        // ---- inp = x @ Wi^T + bc : packed partials then combine ----
        partial_gemm_T2<G>(sWi, sx, sp, w, l);
        GBAR();
        float inp[G];
        #pragma unroll
        for (int r = 0; r < G; r++)
            inp[r] = sp[(r * 4 + 0) * 128 + gtid] + sp[(r * 4 + 1) * 128 + gtid]
                   + sp[(r * 4 + 2) * 128 + gtid] + sp[(r * 4 + 3) * 128 + gtid]
                   + sbc[gtid];

        // prefetch next timestep x (L2 hit; hidden behind inner steps)
        if (t + 1 < TT) {
            #pragma unroll
            for (int r = 0; r < G; r++)
                xreg[r] = g_xproj[xoff[r] + (t + 1) * 128 + gtid];
        }
        GBAR();   // all inp-combine reads of sp done before first inner overwrite

        // ---- inner ODE steps: 3 barriers per step ----
        #pragma unroll 1
        for (int it = 0; it < NS; it++) {
            partial_gemm_T2<G>(sWr, sh, sp, w, l);
            GBAR();

            float d[G];
            #pragma unroll
            for (int r = 0; r < G; r++) {
                const float pre = sp[(r * 4 + 0) * 128 + gtid] + sp[(r * 4 + 1) * 128 + gtid]
                                + sp[(r * 4 + 2) * 128 + gtid] + sp[(r * 4 + 3) * 128 + gtid]
                                + inp[r];
                d[r] = (fast_tanh(pre) - hj[r]) * rtau[r];
            }
            #pragma unroll
            for (int r = 0; r < G; r++) {
                float sq = d[r] * d[r];
                sq += __shfl_xor_sync(0xffffffffu, sq, 16);
                sq += __shfl_xor_sync(0xffffffffu, sq, 8);
                sq += __shfl_xor_sync(0xffffffffu, sq, 4);
                sq += __shfl_xor_sync(0xffffffffu, sq, 2);
                sq += __shfl_xor_sync(0xffffffffu, sq, 1);
                if (l == 0) sred[r * 4 + w] = sq;
            }
            GBAR();
            #pragma unroll
            for (int r = 0; r < G; r++) {
                const float4 s4 = *(const float4*)&sred[r * 4];
                const float mag = sqrtf(s4.x + s4.y + s4.z + s4.w);
                const float coef = __fdividef(DTC, 1.f + 0.2f * mag);
                hj[r] = fmaf(coef, d[r], hj[r]);
                sh[r * 128 + gtid] = hj[r];
            }
            GBAR();   // sh visible (and sp free) before next pass
        }
    }

    #pragma unroll
    for (int r = 0; r < G; r++) {
        const int row = min(grow0 + r, BB - 1);
        g_hT[(s * BB + row) * HH + gtid] = hj[r];
    }
    #undef GBAR
}

__global__ __launch_bounds__(256, 1) void liquid_kernel(
    const float* __restrict__ Wrec, const float* __restrict__ Win_w,
    const float* __restrict__ Win_b, const float* __restrict__ cbias,
    const float* __restrict__ tau_base,
    const float* __restrict__ v1w, const float* __restrict__ v1b,
    const float* __restrict__ v2w, const float* __restrict__ v2b)
{
    extern __shared__ float sm[];
    const int tid = threadIdx.x;
    const int b = blockIdx.x;

    int s, row0;
    if      (b < 21) { s = 0; row0 = b * 13; }
    else if (b < 53) { s = 1; row0 = (b - 21) * 8; }
    else if (b < 96) { s = 2; row0 = (b - 53) * 6; }
    else             { s = 3; row0 = (b - 96) * 5; }

    // stage weights TRANSPOSED: sWT[k*128 + col] = W[col*128 + k]
    const float* Wr = Wrec  + s * 16384;
    const float* Wi = Win_w + s * 16384;
    for (int idx = tid; idx < 16384; idx += 256) {
        const int k = idx >> 7, c = idx & 127;
        sm[OFF_WR + idx] = Wr[c * 128 + k];
        sm[OFF_WI + idx] = Wi[c * 128 + k];
    }
    for (int idx = tid; idx < 32 * 128; idx += 256) {
        int j = idx >> 7, k = idx & 127;
        sm[OFF_V1 + j * 132 + k] = v1w[s * 4096 + idx];
    }
    for (int idx = tid; idx < 128 * 32; idx += 256) {
        int j = idx >> 5, k = idx & 31;
        sm[OFF_V2 + j * 36 + k] = v2w[s * 4096 + idx];
    }
    if (tid < 128) {
        sm[OFF_BC  + tid] = Win_b[s * 128 + tid] + cbias[s * 128 + tid];
        sm[OFF_V2B + tid] = v2b[s * 128 + tid];
        if (tid < 32) sm[OFF_V1B + tid] = v1b[s * 32 + tid];
    }
    __syncthreads();

    const int g = tid >> 7;
    if      (b < 21) { if (!g) run_group<7, 3>(tau_base, 0, row0);
                       else    run_group<6, 3>(tau_base, 0, row0 + 7); }
    else if (b < 53) {          run_group<4, 5>(tau_base, 1, row0 + g * 4); }
    else if (b < 96) {          run_group<3, 7>(tau_base, 2, row0 + g * 3); }
    else             { if (!g) run_group<3, 9>(tau_base, 3, row0);
                       else    run_group<2, 9>(tau_base, 3, row0 + 3); }
}

// ---------------------------------------------------------------------------
// K3: projection + concat + fusion MLP. One block per batch row.
// ---------------------------------------------------------------------------
__global__ __launch_bounds__(128) void head_kernel(
    const float* __restrict__ proj_w, const float* __restrict__ proj_b,
    const float* __restrict__ f1w, const float* __restrict__ f1b,
    const float* __restrict__ f2w, const float* __restrict__ f2b,
    const float* __restrict__ f3w, const float* __restrict__ f3b,
    float* __restrict__ out)
{
    __shared__ float fused[128];
    __shared__ float h1[128];
    __shared__ float h2[64];
    __shared__ float part[2];
    const int b = blockIdx.x;
    const int j = threadIdx.x;
    const int s = j >> 5, i = j & 31;

    {
        const float* h  = &g_hT[(s * BB + b) * HH];
        const float* pw = &proj_w[(s * 32 + i) * HH];
        float a = proj_b[s * 32 + i];
        #pragma unroll 8
        for (int k = 0; k < 128; k++) a = fmaf(h[k], pw[k], a);
        fused[j] = a;
    }
    __syncthreads();
    {
        float a = f1b[j];
        const float* wrow = &f1w[j * 128];
        #pragma unroll 8
        for (int k = 0; k < 128; k++) a = fmaf(fused[k], wrow[k], a);
        h1[j] = fmaxf(a, 0.f);
    }
    __syncthreads();
    if (j < 64) {
        float a = f2b[j];
        const float* wrow = &f2w[j * 128];
        #pragma unroll 8
        for (int k = 0; k < 128; k++) a = fmaf(h1[k], wrow[k], a);
        h2[j] = fmaxf(a, 0.f);
    }
    __syncthreads();
    if (j < 64) {
        float p = h2[j] * f3w[j];
        p += __shfl_xor_sync(0xffffffffu, p, 16);
        p += __shfl_xor_sync(0xffffffffu, p, 8);
        p += __shfl_xor_sync(0xffffffffu, p, 4);
        p += __shfl_xor_sync(0xffffffffu, p, 2);
        p += __shfl_xor_sync(0xffffffffu, p, 1);
        if ((j & 31) == 0) part[j >> 5] = p;
    }
    __syncthreads();
    if (j == 0) out[b] = part[0] + part[1] + f3b[0];
}

// ---------------------------------------------------------------------------
extern "C" void kernel_launch(void* const* d_in, const int* in_sizes, int n_in,
                              void* d_out, int out_size)
{
    const float* x        = (const float*)d_in[0];
    const float* Wp       = (const float*)d_in[1];
    const float* bp       = (const float*)d_in[2];
    const float* Wrec     = (const float*)d_in[3];
    const float* Win_w    = (const float*)d_in[4];
    const float* Win_b    = (const float*)d_in[5];
    const float* cbias    = (const float*)d_in[6];
    const float* tau_base = (const float*)d_in[7];
    const float* vg1_w    = (const float*)d_in[8];
    const float* vg1_b    = (const float*)d_in[9];
    const float* vg2_w    = (const float*)d_in[10];
    const float* vg2_b    = (const float*)d_in[11];
    const float* proj_w   = (const float*)d_in[12];
    const float* proj_b   = (const float*)d_in[13];
    const float* f1w      = (const float*)d_in[14];
    const float* f1b      = (const float*)d_in[15];
    const float* f2w      = (const float*)d_in[16];
    const float* f2b      = (const float*)d_in[17];
    const float* f3w      = (const float*)d_in[18];
    const float* f3b      = (const float*)d_in[19];
    float* out = (float*)d_out;

    cudaFuncSetAttribute(liquid_kernel,
                         cudaFuncAttributeMaxDynamicSharedMemorySize, SMEM_BYTES);

    xproj_kernel<<<(BB * TT) / 32, 128>>>(x, Wp, bp);
    liquid_kernel<<<148, 256, SMEM_BYTES>>>(Wrec, Win_w, Win_b, cbias, tau_base,
                                            vg1_w, vg1_b, vg2_w, vg2_b);
    head_kernel<<<BB, 128>>>(proj_w, proj_b, f1w, f1b, f2w, f2b, f3w, f3b, out);
}

// round 10
// speedup vs baseline: 1.8787x; 1.2459x over previous
#include <cuda_runtime.h>
#include <cuda_bf16.h>
#include <math.h>

#define BB   256
#define TT   512
#define HH   128
#define SS   4
#define DTC  0.1f

// device-global scratch (allocation-free)
__device__ float g_xproj[(size_t)BB * TT * HH];   // 64 MB, [b][t][h]
__device__ float g_hT[SS * BB * HH];

// ---- shared layout (float offsets) ----
#define OFF_WI   0            // 128*128 TRANSPOSED: [k][col]
#define OFF_V1   16384        // 32*132
#define OFF_V2   20608        // 128*36
#define OFF_BC   25216
#define OFF_V2B  25344
#define OFF_V1B  25472
#define OFF_GRP  25504
// per-group: sh 896 | sx 896 | sp 3584 | sqp 896 | sqs 224 | sred 32
#define GRP_STRIDE 6528
#define SMEM_FLOATS (OFF_GRP + 2 * GRP_STRIDE)
#define SMEM_BYTES  (SMEM_FLOATS * 4)

__device__ __forceinline__ float fast_tanh(float x) {
    float ax = fminf(fabsf(x), 12.0f);
    float e  = __expf(2.0f * ax);
    float r  = __fdividef(e - 1.0f, e + 1.0f);
    return copysignf(r, x);
}

// ---------------------------------------------------------------------------
// K1: x_proj = x @ Wp^T + bp
// ---------------------------------------------------------------------------
__global__ __launch_bounds__(128) void xproj_kernel(
    const float* __restrict__ x, const float* __restrict__ Wp,
    const float* __restrict__ bp)
{
    __shared__ float sW[128 * 36];
    __shared__ float sx[32 * 32];
    __shared__ float sb[128];
    const int tid = threadIdx.x;

    for (int idx = tid; idx < 128 * 32; idx += 128) {
        int j = idx >> 5, k = idx & 31;
        sW[j * 36 + k] = Wp[idx];
    }
    sb[tid] = bp[tid];
    const size_t base = (size_t)blockIdx.x * 32;
    for (int idx = tid; idx < 1024; idx += 128)
        sx[idx] = x[base * 32 + idx];
    __syncthreads();

    float acc[32];
    const float b = sb[tid];
    #pragma unroll
    for (int r = 0; r < 32; r++) acc[r] = b;

    #pragma unroll 2
    for (int kk = 0; kk < 32; kk += 4) {
        const float4 w4 = *(const float4*)&sW[tid * 36 + kk];
        #pragma unroll
        for (int r = 0; r < 32; r++) {
            const float4 x4 = *(const float4*)&sx[r * 32 + kk];
            acc[r] = fmaf(x4.x, w4.x, acc[r]);
            acc[r] = fmaf(x4.y, w4.y, acc[r]);
            acc[r] = fmaf(x4.z, w4.z, acc[r]);
            acc[r] = fmaf(x4.w, w4.w, acc[r]);
        }
    }
    #pragma unroll
    for (int r = 0; r < 32; r++)
        g_xproj[(base + r) * HH + tid] = acc[r];
}

// ---------------------------------------------------------------------------
// Packed-pair k-split partial GEMM, weights from SMEM (used for inp pass).
// Thread (w,l) owns cols 4l..4l+3 over k in [32w,32w+32) for G rows.
// ---------------------------------------------------------------------------
template<int G>
__device__ __forceinline__ void partial_gemm_T2(
    const float* __restrict__ sWT, const float* __restrict__ svec,
    float* __restrict__ sp, int w, int l)
{
    unsigned long long accA[G], accB[G];
    #pragma unroll
    for (int r = 0; r < G; r++) { accA[r] = 0ull; accB[r] = 0ull; }

    const int k0 = 32 * w;
    const int c0 = 4 * l;
    #pragma unroll
    for (int kk = 0; kk < 8; kk++) {
        const ulonglong2 w0 = *(const ulonglong2*)&sWT[(k0 + 4 * kk + 0) * 128 + c0];
        const ulonglong2 w1 = *(const ulonglong2*)&sWT[(k0 + 4 * kk + 1) * 128 + c0];
        const ulonglong2 w2 = *(const ulonglong2*)&sWT[(k0 + 4 * kk + 2) * 128 + c0];
        const ulonglong2 w3 = *(const ulonglong2*)&sWT[(k0 + 4 * kk + 3) * 128 + c0];
        #pragma unroll
        for (int r = 0; r < G; r++) {
            const float4 x4 = *(const float4*)&svec[r * 128 + k0 + 4 * kk];
            unsigned long long px, py, pz, pw2;
            asm("mov.b64 %0, {%1, %1};" : "=l"(px)  : "f"(x4.x));
            asm("mov.b64 %0, {%1, %1};" : "=l"(py)  : "f"(x4.y));
            asm("mov.b64 %0, {%1, %1};" : "=l"(pz)  : "f"(x4.z));
            asm("mov.b64 %0, {%1, %1};" : "=l"(pw2) : "f"(x4.w));
            asm("fma.rn.f32x2 %0, %1, %2, %0;" : "+l"(accA[r]) : "l"(w0.x), "l"(px));
            asm("fma.rn.f32x2 %0, %1, %2, %0;" : "+l"(accB[r]) : "l"(w0.y), "l"(px));
            asm("fma.rn.f32x2 %0, %1, %2, %0;" : "+l"(accA[r]) : "l"(w1.x), "l"(py));
            asm("fma.rn.f32x2 %0, %1, %2, %0;" : "+l"(accB[r]) : "l"(w1.y), "l"(py));
            asm("fma.rn.f32x2 %0, %1, %2, %0;" : "+l"(accA[r]) : "l"(w2.x), "l"(pz));
            asm("fma.rn.f32x2 %0, %1, %2, %0;" : "+l"(accB[r]) : "l"(w2.y), "l"(pz));
            asm("fma.rn.f32x2 %0, %1, %2, %0;" : "+l"(accA[r]) : "l"(w3.x), "l"(pw2));
            asm("fma.rn.f32x2 %0, %1, %2, %0;" : "+l"(accB[r]) : "l"(w3.y), "l"(pw2));
        }
    }
    #pragma unroll
    for (int r = 0; r < G; r++) {
        ulonglong2 st;
        st.x = accA[r];
        st.y = accB[r];
        *(ulonglong2*)&sp[(r * 4 + w) * 128 + c0] = st;
    }
}

// ---------------------------------------------------------------------------
// Packed-pair partial GEMM with REGISTER-RESIDENT weights (inner passes).
// wrA[k] = packed cols (c0,c0+1) at k0+k; wrB[k] = cols (c0+2,c0+3).
// Identical k-summation order to the SMEM version.
// ---------------------------------------------------------------------------
template<int G>
__device__ __forceinline__ void partial_gemm_reg(
    const unsigned long long* __restrict__ wrA,
    const unsigned long long* __restrict__ wrB,
    const float* __restrict__ svec, float* __restrict__ sp, int w, int l)
{
    unsigned long long accA[G], accB[G];
    #pragma unroll
    for (int r = 0; r < G; r++) { accA[r] = 0ull; accB[r] = 0ull; }

    const int k0 = 32 * w;
    const int c0 = 4 * l;
    #pragma unroll
    for (int kk = 0; kk < 8; kk++) {
        #pragma unroll
        for (int r = 0; r < G; r++) {
            const float4 x4 = *(const float4*)&svec[r * 128 + k0 + 4 * kk];
            unsigned long long px, py, pz, pw2;
            asm("mov.b64 %0, {%1, %1};" : "=l"(px)  : "f"(x4.x));
            asm("mov.b64 %0, {%1, %1};" : "=l"(py)  : "f"(x4.y));
            asm("mov.b64 %0, {%1, %1};" : "=l"(pz)  : "f"(x4.z));
            asm("mov.b64 %0, {%1, %1};" : "=l"(pw2) : "f"(x4.w));
            asm("fma.rn.f32x2 %0, %1, %2, %0;" : "+l"(accA[r]) : "l"(wrA[4*kk+0]), "l"(px));
            asm("fma.rn.f32x2 %0, %1, %2, %0;" : "+l"(accB[r]) : "l"(wrB[4*kk+0]), "l"(px));
            asm("fma.rn.f32x2 %0, %1, %2, %0;" : "+l"(accA[r]) : "l"(wrA[4*kk+1]), "l"(py));
            asm("fma.rn.f32x2 %0, %1, %2, %0;" : "+l"(accB[r]) : "l"(wrB[4*kk+1]), "l"(py));
            asm("fma.rn.f32x2 %0, %1, %2, %0;" : "+l"(accA[r]) : "l"(wrA[4*kk+2]), "l"(pz));
            asm("fma.rn.f32x2 %0, %1, %2, %0;" : "+l"(accB[r]) : "l"(wrB[4*kk+2]), "l"(pz));
            asm("fma.rn.f32x2 %0, %1, %2, %0;" : "+l"(accA[r]) : "l"(wrA[4*kk+3]), "l"(pw2));
            asm("fma.rn.f32x2 %0, %1, %2, %0;" : "+l"(accB[r]) : "l"(wrB[4*kk+3]), "l"(pw2));
        }
    }
    #pragma unroll
    for (int r = 0; r < G; r++) {
        ulonglong2 st;
        st.x = accA[r];
        st.y = accB[r];
        *(ulonglong2*)&sp[(r * 4 + w) * 128 + c0] = st;
    }
}

// ---------------------------------------------------------------------------
// K2: persistent liquid recurrence. 256 threads = 2 independent 128-thread
// groups (named barriers) sharing one SMEM weight copy; Wrec in registers.
// ---------------------------------------------------------------------------
template<int G, int NS>
__device__ __forceinline__ void run_group(
    const float* __restrict__ Wrec, const float* __restrict__ tau_base,
    int s, int grow0)
{
    extern __shared__ float sm[];
    const int tid  = threadIdx.x;
    const int g    = tid >> 7;
    const int gtid = tid & 127;
    const int w = gtid >> 5, l = gtid & 31;

    float* gs   = sm + OFF_GRP + g * GRP_STRIDE;
    float* sh   = gs;
    float* sx   = gs + 896;
    float* sp   = gs + 1792;
    float* sqp  = gs + 5376;
    float* sqs  = gs + 6272;
    float* sred = gs + 6496;
    const float* sWi  = sm + OFF_WI;
    const float* sV1  = sm + OFF_V1;
    const float* sV2  = sm + OFF_V2;
    const float* sbc  = sm + OFF_BC;
    const float* sv2b = sm + OFF_V2B;
    const float* sv1b = sm + OFF_V1B;

    const int barid = g + 1;
    #define GBAR() asm volatile("bar.sync %0, 128;" :: "r"(barid) : "memory")

    // ---- Wrec slice into registers: cols 4l..4l+3, k in [32w,32w+32) ----
    unsigned long long wrA[32], wrB[32];
    {
        const float* WrS = Wrec + s * 16384;
        const int k0 = 32 * w, c0 = 4 * l;
        #pragma unroll
        for (int k = 0; k < 32; k++) {
            const float a0 = WrS[(c0 + 0) * 128 + k0 + k];
            const float a1 = WrS[(c0 + 1) * 128 + k0 + k];
            const float b0 = WrS[(c0 + 2) * 128 + k0 + k];
            const float b1 = WrS[(c0 + 3) * 128 + k0 + k];
            asm("mov.b64 %0, {%1, %2};" : "=l"(wrA[k]) : "f"(a0), "f"(a1));
            asm("mov.b64 %0, {%1, %2};" : "=l"(wrB[k]) : "f"(b0), "f"(b1));
        }
    }

    const float tb = tau_base[s * 128 + gtid];
    float hj[G], xreg[G];
    int xoff[G];
    #pragma unroll
    for (int r = 0; r < G; r++) {
        hj[r] = 0.f;
        sh[r * 128 + gtid] = 0.f;
        const int row = min(grow0 + r, BB - 1);
        xoff[r] = row * (TT * HH);
        xreg[r] = g_xproj[xoff[r] + gtid];
    }
    GBAR();

    for (int t = 0; t < TT; t++) {
        #pragma unroll
        for (int r = 0; r < G; r++) sx[r * 128 + gtid] = xreg[r];
        GBAR();

        // ---- gate layer 1 partials: thread l = gate row, k-chunk w ----
        {
            float qp[G];
            #pragma unroll
            for (int r = 0; r < G; r++) qp[r] = 0.f;
            const int k0 = w * 32;
            #pragma unroll
            for (int kk = 0; kk < 32; kk += 4) {
                const float4 v4 = *(const float4*)&sV1[l * 132 + k0 + kk];
                #pragma unroll
                for (int r = 0; r < G; r++) {
                    const float4 x4 = *(const float4*)&sx[r * 128 + k0 + kk];
                    qp[r] = fmaf(x4.x, v4.x, qp[r]);
                    qp[r] = fmaf(x4.y, v4.y, qp[r]);
                    qp[r] = fmaf(x4.z, v4.z, qp[r]);
                    qp[r] = fmaf(x4.w, v4.w, qp[r]);
                }
            }
            #pragma unroll
            for (int r = 0; r < G; r++) sqp[w * 224 + r * 32 + l] = qp[r];
        }
        GBAR();
        if (gtid < 32) {
            #pragma unroll
            for (int r = 0; r < G; r++) {
                float q = sqp[r * 32 + gtid] + sqp[224 + r * 32 + gtid]
                        + sqp[448 + r * 32 + gtid] + sqp[672 + r * 32 + gtid]
                        + sv1b[gtid];
                sqs[r * 32 + gtid] = fmaxf(q, 0.f);
            }
        }
        GBAR();

        // ---- gate layer 2 -> rtau (owner column gtid) ----
        float rtau[G];
        {
            float va[G];
            #pragma unroll
            for (int r = 0; r < G; r++) va[r] = sv2b[gtid];
            #pragma unroll
            for (int ii = 0; ii < 32; ii += 4) {
                const float4 w4 = *(const float4*)&sV2[gtid * 36 + ii];
                #pragma unroll
                for (int r = 0; r < G; r++) {
                    const float4 q4 = *(const float4*)&sqs[r * 32 + ii];
                    va[r] = fmaf(q4.x, w4.x, va[r]);
                    va[r] = fmaf(q4.y, w4.y, va[r]);
                    va[r] = fmaf(q4.z, w4.z, va[r]);
                    va[r] = fmaf(q4.w, w4.w, va[r]);
                }
            }
            #pragma unroll
            for (int r = 0; r < G; r++) {
                const float vol = __fdividef(1.f, 1.f + __expf(-va[r]));
                float ta = tb * (0.2f + 1.8f * (1.f - vol));
                ta = fminf(fmaxf(ta, 0.1f), 10.f);
                rtau[r] = __frcp_rn(ta);
            }
        }

        // ---- inp = x @ Wi^T + bc : smem-weight partials then combine ----
        partial_gemm_T2<G>(sWi, sx, sp, w, l);
        GBAR();
        float inp[G];
        #pragma unroll
        for (int r = 0; r < G; r++)
            inp[r] = sp[(r * 4 + 0) * 128 + gtid] + sp[(r * 4 + 1) * 128 + gtid]
                   + sp[(r * 4 + 2) * 128 + gtid] + sp[(r * 4 + 3) * 128 + gtid]
                   + sbc[gtid];

        // prefetch next timestep x (L2 hit; hidden behind inner steps)
        if (t + 1 < TT) {
            #pragma unroll
            for (int r = 0; r < G; r++)
                xreg[r] = g_xproj[xoff[r] + (t + 1) * 128 + gtid];
        }
        GBAR();   // all inp-combine reads of sp done before first inner overwrite

        // ---- inner ODE steps: register-weight GEMM, 3 barriers per step ----
        #pragma unroll 1
        for (int it = 0; it < NS; it++) {
            partial_gemm_reg<G>(wrA, wrB, sh, sp, w, l);
            GBAR();

            float d[G];
            #pragma unroll
            for (int r = 0; r < G; r++) {
                const float pre = sp[(r * 4 + 0) * 128 + gtid] + sp[(r * 4 + 1) * 128 + gtid]
                                + sp[(r * 4 + 2) * 128 + gtid] + sp[(r * 4 + 3) * 128 + gtid]
                                + inp[r];
                d[r] = (fast_tanh(pre) - hj[r]) * rtau[r];
            }
            #pragma unroll
            for (int r = 0; r < G; r++) {
                float sq = d[r] * d[r];
                sq += __shfl_xor_sync(0xffffffffu, sq, 16);
                sq += __shfl_xor_sync(0xffffffffu, sq, 8);
                sq += __shfl_xor_sync(0xffffffffu, sq, 4);
                sq += __shfl_xor_sync(0xffffffffu, sq, 2);
                sq += __shfl_xor_sync(0xffffffffu, sq, 1);
                if (l == 0) sred[r * 4 + w] = sq;
            }
            GBAR();
            #pragma unroll
            for (int r = 0; r < G; r++) {
                const float4 s4 = *(const float4*)&sred[r * 4];
                const float mag = sqrtf(s4.x + s4.y + s4.z + s4.w);
                const float coef = __fdividef(DTC, 1.f + 0.2f * mag);
                hj[r] = fmaf(coef, d[r], hj[r]);
                sh[r * 128 + gtid] = hj[r];
            }
            GBAR();   // sh visible (and sp free) before next pass
        }
    }

    #pragma unroll
    for (int r = 0; r < G; r++) {
        const int row = min(grow0 + r, BB - 1);
        g_hT[(s * BB + row) * HH + gtid] = hj[r];
    }
    #undef GBAR
}

__global__ __launch_bounds__(256, 1) void liquid_kernel(
    const float* __restrict__ Wrec, const float* __restrict__ Win_w,
    const float* __restrict__ Win_b, const float* __restrict__ cbias,
    const float* __restrict__ tau_base,
    const float* __restrict__ v1w, const float* __restrict__ v1b,
    const float* __restrict__ v2w, const float* __restrict__ v2b)
{
    extern __shared__ float sm[];
    const int tid = threadIdx.x;
    const int b = blockIdx.x;

    int s, row0;
    if      (b < 21) { s = 0; row0 = b * 13; }
    else if (b < 53) { s = 1; row0 = (b - 21) * 8; }
    else if (b < 96) { s = 2; row0 = (b - 53) * 6; }
    else             { s = 3; row0 = (b - 96) * 5; }

    // stage Win TRANSPOSED: sWT[k*128 + col] = W[col*128 + k]
    const float* Wi = Win_w + s * 16384;
    for (int idx = tid; idx < 16384; idx += 256) {
        const int k = idx >> 7, c = idx & 127;
        sm[OFF_WI + idx] = Wi[c * 128 + k];
    }
    for (int idx = tid; idx < 32 * 128; idx += 256) {
        int j = idx >> 7, k = idx & 127;
        sm[OFF_V1 + j * 132 + k] = v1w[s * 4096 + idx];
    }
    for (int idx = tid; idx < 128 * 32; idx += 256) {
        int j = idx >> 5, k = idx & 31;
        sm[OFF_V2 + j * 36 + k] = v2w[s * 4096 + idx];
    }
    if (tid < 128) {
        sm[OFF_BC  + tid] = Win_b[s * 128 + tid] + cbias[s * 128 + tid];
        sm[OFF_V2B + tid] = v2b[s * 128 + tid];
        if (tid < 32) sm[OFF_V1B + tid] = v1b[s * 32 + tid];
    }
    __syncthreads();

    const int g = tid >> 7;
    if      (b < 21) { if (!g) run_group<7, 3>(Wrec, tau_base, 0, row0);
                       else    run_group<6, 3>(Wrec, tau_base, 0, row0 + 7); }
    else if (b < 53) {          run_group<4, 5>(Wrec, tau_base, 1, row0 + g * 4); }
    else if (b < 96) {          run_group<3, 7>(Wrec, tau_base, 2, row0 + g * 3); }
    else             { if (!g) run_group<3, 9>(Wrec, tau_base, 3, row0);
                       else    run_group<2, 9>(Wrec, tau_base, 3, row0 + 3); }
}

// ---------------------------------------------------------------------------
// K3: projection + concat + fusion MLP. One block per batch row.
// ---------------------------------------------------------------------------
__global__ __launch_bounds__(128) void head_kernel(
    const float* __restrict__ proj_w, const float* __restrict__ proj_b,
    const float* __restrict__ f1w, const float* __restrict__ f1b,
    const float* __restrict__ f2w, const float* __restrict__ f2b,
    const float* __restrict__ f3w, const float* __restrict__ f3b,
    float* __restrict__ out)
{
    __shared__ float fused[128];
    __shared__ float h1[128];
    __shared__ float h2[64];
    __shared__ float part[2];
    const int b = blockIdx.x;
    const int j = threadIdx.x;
    const int s = j >> 5, i = j & 31;

    {
        const float* h  = &g_hT[(s * BB + b) * HH];
        const float* pw = &proj_w[(s * 32 + i) * HH];
        float a = proj_b[s * 32 + i];
        #pragma unroll 8
        for (int k = 0; k < 128; k++) a = fmaf(h[k], pw[k], a);
        fused[j] = a;
    }
    __syncthreads();
    {
        float a = f1b[j];
        const float* wrow = &f1w[j * 128];
        #pragma unroll 8
        for (int k = 0; k < 128; k++) a = fmaf(fused[k], wrow[k], a);
        h1[j] = fmaxf(a, 0.f);
    }
    __syncthreads();
    if (j < 64) {
        float a = f2b[j];
        const float* wrow = &f2w[j * 128];
        #pragma unroll 8
        for (int k = 0; k < 128; k++) a = fmaf(h1[k], wrow[k], a);
        h2[j] = fmaxf(a, 0.f);
    }
    __syncthreads();
    if (j < 64) {
        float p = h2[j] * f3w[j];
        p += __shfl_xor_sync(0xffffffffu, p, 16);
        p += __shfl_xor_sync(0xffffffffu, p, 8);
        p += __shfl_xor_sync(0xffffffffu, p, 4);
        p += __shfl_xor_sync(0xffffffffu, p, 2);
        p += __shfl_xor_sync(0xffffffffu, p, 1);
        if ((j & 31) == 0) part[j >> 5] = p;
    }
    __syncthreads();
    if (j == 0) out[b] = part[0] + part[1] + f3b[0];
}

// ---------------------------------------------------------------------------
extern "C" void kernel_launch(void* const* d_in, const int* in_sizes, int n_in,
                              void* d_out, int out_size)
{
    const float* x        = (const float*)d_in[0];
    const float* Wp       = (const float*)d_in[1];
    const float* bp       = (const float*)d_in[2];
    const float* Wrec     = (const float*)d_in[3];
    const float* Win_w    = (const float*)d_in[4];
    const float* Win_b    = (const float*)d_in[5];
    const float* cbias    = (const float*)d_in[6];
    const float* tau_base = (const float*)d_in[7];
    const float* vg1_w    = (const float*)d_in[8];
    const float* vg1_b    = (const float*)d_in[9];
    const float* vg2_w    = (const float*)d_in[10];
    const float* vg2_b    = (const float*)d_in[11];
    const float* proj_w   = (const float*)d_in[12];
    const float* proj_b   = (const float*)d_in[13];
    const float* f1w      = (const float*)d_in[14];
    const float* f1b      = (const float*)d_in[15];
    const float* f2w      = (const float*)d_in[16];
    const float* f2b      = (const float*)d_in[17];
    const float* f3w      = (const float*)d_in[18];
    const float* f3b      = (const float*)d_in[19];
    float* out = (float*)d_out;

    cudaFuncSetAttribute(liquid_kernel,
                         cudaFuncAttributeMaxDynamicSharedMemorySize, SMEM_BYTES);

    xproj_kernel<<<(BB * TT) / 32, 128>>>(x, Wp, bp);
    liquid_kernel<<<148, 256, SMEM_BYTES>>>(Wrec, Win_w, Win_b, cbias, tau_base,
                                            vg1_w, vg1_b, vg2_w, vg2_b);
    head_kernel<<<BB, 128>>>(proj_w, proj_b, f1w, f1b, f2w, f2b, f3w, f3b, out);
}